// round 1
// baseline (speedup 1.0000x reference)
#include <cuda_runtime.h>
#include <math.h>

#define NTOK 4096          // B*T = 2*2048
#define CEMB 768
#define TSEQ 2048
#define NHEAD 12
#define HDIM 64

// ---------------------------------------------------------------------------
// Scratch (static device globals: allocation-free per harness rules)
// ---------------------------------------------------------------------------
__device__ float g_ln [NTOK * CEMB];       // LN output (reused for LN1 and LN2)
__device__ float g_qkv[NTOK * 3 * CEMB];   // QKV projection
__device__ float g_att[NTOK * CEMB];       // attention output
__device__ float g_x1 [NTOK * CEMB];       // x + attn  (first residual)
__device__ float g_fc [NTOK * 4 * CEMB];   // GELU(fc) activations

// ---------------------------------------------------------------------------
// LayerNorm: one block per row of 768
// ---------------------------------------------------------------------------
__global__ __launch_bounds__(256) void ln_kernel(
    const float* __restrict__ x, const float* __restrict__ g,
    const float* __restrict__ b, float* __restrict__ out)
{
    const int row = blockIdx.x;
    const int tid = threadIdx.x;
    const float* xr = x + (size_t)row * CEMB;

    float v0 = xr[tid], v1 = xr[tid + 256], v2 = xr[tid + 512];
    float s  = v0 + v1 + v2;
    float sq = v0 * v0 + v1 * v1 + v2 * v2;

#pragma unroll
    for (int o = 16; o > 0; o >>= 1) {
        s  += __shfl_xor_sync(0xffffffffu, s,  o);
        sq += __shfl_xor_sync(0xffffffffu, sq, o);
    }

    __shared__ float rs[8], rq[8];
    __shared__ float s_mu, s_rstd;
    const int wid = tid >> 5, lid = tid & 31;
    if (lid == 0) { rs[wid] = s; rq[wid] = sq; }
    __syncthreads();
    if (tid == 0) {
        float ts = 0.f, tq = 0.f;
#pragma unroll
        for (int i = 0; i < 8; i++) { ts += rs[i]; tq += rq[i]; }
        float mu  = ts * (1.0f / CEMB);
        float var = tq * (1.0f / CEMB) - mu * mu;
        s_mu = mu;
        s_rstd = rsqrtf(var + 1e-5f);
    }
    __syncthreads();
    const float mu = s_mu, r = s_rstd;
    float* orow = out + (size_t)row * CEMB;
    orow[tid      ] = (v0 - mu) * r * g[tid      ] + b[tid      ];
    orow[tid + 256] = (v1 - mu) * r * g[tid + 256] + b[tid + 256];
    orow[tid + 512] = (v2 - mu) * r * g[tid + 512] + b[tid + 512];
}

// ---------------------------------------------------------------------------
// GELU (tanh approximation, matches reference)
// ---------------------------------------------------------------------------
__device__ __forceinline__ float gelu_f(float x) {
    const float c = 0.7978845608028654f;  // sqrt(2/pi)
    float x3 = x * x * x;
    return 0.5f * x * (1.0f + tanhf(c * (x + 0.044715f * x3)));
}

// ---------------------------------------------------------------------------
// SGEMM: C[M,N] = A[M,K] @ B[K,N] + bias  (+residual | GELU)
// 128x128 tile, BK=8, 256 threads, 8x8 microtile. All dims divide evenly.
// EPI: 0 = bias, 1 = bias + residual, 2 = GELU(bias + acc)
// ---------------------------------------------------------------------------
template <int EPI>
__global__ __launch_bounds__(256) void sgemm_kernel(
    int M, int N, int K,
    const float* __restrict__ A, const float* __restrict__ B,
    const float* __restrict__ bias, const float* __restrict__ res,
    float* __restrict__ Cout)
{
    __shared__ float As[8][128];
    __shared__ float Bs[8][128];

    const int tid = threadIdx.x;
    const int cCol = blockIdx.x * 128;
    const int cRow = blockIdx.y * 128;

    const int irA = tid >> 1;          // 0..127 (A row within tile)
    const int icA = (tid & 1) * 4;     // 0 or 4 (A k-offset)
    const int irB = tid >> 5;          // 0..7   (B k-row)
    const int icB = (tid & 31) * 4;    // 0..124 (B col within tile)
    const int tr  = tid >> 4;          // 0..15
    const int tc  = tid & 15;          // 0..15

    float acc[8][8];
#pragma unroll
    for (int i = 0; i < 8; i++)
#pragma unroll
        for (int j = 0; j < 8; j++) acc[i][j] = 0.f;

    const float* Ab = A + (size_t)(cRow + irA) * K + icA;
    const float* Bb = B + (size_t)irB * N + cCol + icB;

    for (int kt = 0; kt < K; kt += 8) {
        float4 a4 = *(const float4*)(Ab + kt);
        As[icA + 0][irA] = a4.x;
        As[icA + 1][irA] = a4.y;
        As[icA + 2][irA] = a4.z;
        As[icA + 3][irA] = a4.w;
        *(float4*)&Bs[irB][icB] = *(const float4*)(Bb + (size_t)kt * N);
        __syncthreads();

#pragma unroll
        for (int k = 0; k < 8; k++) {
            float4 a0 = *(float4*)&As[k][tr * 8];
            float4 a1 = *(float4*)&As[k][tr * 8 + 4];
            float4 b0 = *(float4*)&Bs[k][tc * 8];
            float4 b1 = *(float4*)&Bs[k][tc * 8 + 4];
            float ra[8] = {a0.x, a0.y, a0.z, a0.w, a1.x, a1.y, a1.z, a1.w};
            float rb[8] = {b0.x, b0.y, b0.z, b0.w, b1.x, b1.y, b1.z, b1.w};
#pragma unroll
            for (int i = 0; i < 8; i++)
#pragma unroll
                for (int j = 0; j < 8; j++)
                    acc[i][j] += ra[i] * rb[j];
        }
        __syncthreads();
    }

#pragma unroll
    for (int i = 0; i < 8; i++) {
        const int row = cRow + tr * 8 + i;
#pragma unroll
        for (int j = 0; j < 8; j++) {
            const int col = cCol + tc * 8 + j;
            float v = acc[i][j] + bias[col];
            if (EPI == 1) v += res[(size_t)row * N + col];
            if (EPI == 2) v = gelu_f(v);
            Cout[(size_t)row * N + col] = v;
        }
    }
}

// ---------------------------------------------------------------------------
// Causal attention, flash-style streaming softmax.
// grid = (T/128, NHEAD, B); block = 128; one thread per query row.
// qkv layout: [(b*T + t) * 2304]: q at h*64, k at 768+h*64, v at 1536+h*64.
// ---------------------------------------------------------------------------
__global__ __launch_bounds__(128) void attn_kernel(
    const float* __restrict__ qkv, float* __restrict__ y)
{
    __shared__ float Ks[64][64];
    __shared__ float Vs[64][64];

    const int tid   = threadIdx.x;
    const int hh    = blockIdx.y;
    const int bb    = blockIdx.z;
    const int q_idx = blockIdx.x * 128 + tid;
    const int kmax  = blockIdx.x * 128 + 127;
    const float scale = 0.125f;  // 1/sqrt(64)

    // load q into registers
    float4 qr[16];
    {
        const float* qp = qkv + ((size_t)(bb * TSEQ + q_idx)) * 2304 + hh * 64;
#pragma unroll
        for (int i = 0; i < 16; i++) qr[i] = *(const float4*)(qp + i * 4);
    }

    float m = -INFINITY, l = 0.f;
    float4 acc[16];
#pragma unroll
    for (int i = 0; i < 16; i++) acc[i] = make_float4(0.f, 0.f, 0.f, 0.f);

    const int r  = tid >> 1;
    const int cp = (tid & 1) * 32;

    for (int j0 = 0; j0 <= kmax; j0 += 64) {
        __syncthreads();
        // cooperative load of K/V tile (64 keys x 64 dims)
        const float* krow = qkv + ((size_t)(bb * TSEQ + j0 + r)) * 2304 + 768 + hh * 64 + cp;
        const float* vrow = krow + 768;
#pragma unroll
        for (int i = 0; i < 8; i++) {
            *(float4*)&Ks[r][cp + i * 4] = *(const float4*)(krow + i * 4);
            *(float4*)&Vs[r][cp + i * 4] = *(const float4*)(vrow + i * 4);
        }
        __syncthreads();

        const int jrem = q_idx - j0 + 1;
        if (jrem > 0) {
            const int jend = jrem < 64 ? jrem : 64;
            for (int j = 0; j < jend; j++) {
                float s = 0.f;
#pragma unroll
                for (int i = 0; i < 16; i++) {
                    float4 kv = *(float4*)&Ks[j][i * 4];
                    s += qr[i].x * kv.x + qr[i].y * kv.y
                       + qr[i].z * kv.z + qr[i].w * kv.w;
                }
                s *= scale;
                if (s > m) {
                    float f = __expf(m - s);
                    l *= f;
#pragma unroll
                    for (int i = 0; i < 16; i++) {
                        acc[i].x *= f; acc[i].y *= f;
                        acc[i].z *= f; acc[i].w *= f;
                    }
                    m = s;
                }
                float p = __expf(s - m);
                l += p;
#pragma unroll
                for (int i = 0; i < 16; i++) {
                    float4 vv = *(float4*)&Vs[j][i * 4];
                    acc[i].x += p * vv.x; acc[i].y += p * vv.y;
                    acc[i].z += p * vv.z; acc[i].w += p * vv.w;
                }
            }
        }
    }

    const float inv = 1.0f / l;
    float* op = y + ((size_t)(bb * TSEQ + q_idx)) * CEMB + hh * 64;
#pragma unroll
    for (int i = 0; i < 16; i++) {
        float4 o = acc[i];
        o.x *= inv; o.y *= inv; o.z *= inv; o.w *= inv;
        *(float4*)(op + i * 4) = o;
    }
}

// ---------------------------------------------------------------------------
// Launch
// ---------------------------------------------------------------------------
extern "C" void kernel_launch(void* const* d_in, const int* in_sizes, int n_in,
                              void* d_out, int out_size)
{
    const float* x           = (const float*)d_in[0];
    const float* ln1_g       = (const float*)d_in[1];
    const float* ln1_b       = (const float*)d_in[2];
    const float* w_attn      = (const float*)d_in[3];
    const float* b_attn      = (const float*)d_in[4];
    const float* w_attn_proj = (const float*)d_in[5];
    const float* b_attn_proj = (const float*)d_in[6];
    const float* ln2_g       = (const float*)d_in[7];
    const float* ln2_b       = (const float*)d_in[8];
    const float* w_fc        = (const float*)d_in[9];
    const float* b_fc        = (const float*)d_in[10];
    const float* w_mlp_proj  = (const float*)d_in[11];
    const float* b_mlp_proj  = (const float*)d_in[12];
    float* out = (float*)d_out;

    float *p_ln, *p_qkv, *p_att, *p_x1, *p_fc;
    cudaGetSymbolAddress((void**)&p_ln,  g_ln);
    cudaGetSymbolAddress((void**)&p_qkv, g_qkv);
    cudaGetSymbolAddress((void**)&p_att, g_att);
    cudaGetSymbolAddress((void**)&p_x1,  g_x1);
    cudaGetSymbolAddress((void**)&p_fc,  g_fc);

    // 1. LN1
    ln_kernel<<<NTOK, 256>>>(x, ln1_g, ln1_b, p_ln);

    // 2. QKV = LN1 @ w_attn + b_attn          [4096, 2304]
    sgemm_kernel<0><<<dim3(2304 / 128, NTOK / 128), 256>>>(
        NTOK, 2304, CEMB, p_ln, w_attn, b_attn, nullptr, p_qkv);

    // 3. causal attention                      [4096, 768]
    attn_kernel<<<dim3(TSEQ / 128, NHEAD, 2), 128>>>(p_qkv, p_att);

    // 4. x1 = x + att @ w_attn_proj + b        [4096, 768]
    sgemm_kernel<1><<<dim3(CEMB / 128, NTOK / 128), 256>>>(
        NTOK, CEMB, CEMB, p_att, w_attn_proj, b_attn_proj, x, p_x1);

    // 5. LN2
    ln_kernel<<<NTOK, 256>>>(p_x1, ln2_g, ln2_b, p_ln);

    // 6. fc = GELU(LN2 @ w_fc + b_fc)          [4096, 3072]
    sgemm_kernel<2><<<dim3(3072 / 128, NTOK / 128), 256>>>(
        NTOK, 3072, CEMB, p_ln, w_fc, b_fc, nullptr, p_fc);

    // 7. out = x1 + fc @ w_mlp_proj + b        [4096, 768]
    sgemm_kernel<1><<<dim3(CEMB / 128, NTOK / 128), 256>>>(
        NTOK, CEMB, 4 * CEMB, p_fc, w_mlp_proj, b_mlp_proj, p_x1, out);
}

// round 6
// speedup vs baseline: 2.0671x; 2.0671x over previous
#include <cuda_runtime.h>
#include <cuda_fp16.h>
#include <cstdint>
#include <math.h>

#define NTOK 4096          // B*T
#define CEMB 768
#define TSEQ 2048
#define NHEAD 12
#define HDIM 64

// ---------------------------------------------------------------------------
// Scratch
// ---------------------------------------------------------------------------
__device__ __half g_lnh [NTOK * CEMB];
__device__ float  g_qkv [NTOK * 3 * CEMB];
__device__ __half g_atth[NTOK * CEMB];
__device__ float  g_x1  [NTOK * CEMB];
__device__ __half g_fch [NTOK * 4 * CEMB];
__device__ __half g_wTa [3 * CEMB * CEMB];   // [2304][768]
__device__ __half g_wTp [CEMB * CEMB];       // [768][768]
__device__ __half g_wTf [4 * CEMB * CEMB];   // [3072][768]
__device__ __half g_wTm [CEMB * 4 * CEMB];   // [768][3072]

// ---------------------------------------------------------------------------
// PTX helpers
// ---------------------------------------------------------------------------
__device__ __forceinline__ uint32_t smem_u32(const void* p) {
    uint32_t a;
    asm("{ .reg .u64 t; cvta.to.shared.u64 t, %1; cvt.u32.u64 %0, t; }"
        : "=r"(a) : "l"(p));
    return a;
}
__device__ __forceinline__ void cp_async16(uint32_t saddr, const void* g) {
    asm volatile("cp.async.cg.shared.global [%0], [%1], 16;" :: "r"(saddr), "l"(g));
}
#define CP_COMMIT() asm volatile("cp.async.commit_group;")
#define CP_WAIT(n)  asm volatile("cp.async.wait_group %0;" :: "n"(n))

__device__ __forceinline__ void ldsm4(uint32_t* r, uint32_t addr) {
    asm volatile("ldmatrix.sync.aligned.m8n8.x4.shared.b16 {%0,%1,%2,%3}, [%4];"
        : "=r"(r[0]), "=r"(r[1]), "=r"(r[2]), "=r"(r[3]) : "r"(addr));
}
__device__ __forceinline__ void mma16816(float* c, const uint32_t* a, const uint32_t* b) {
    asm volatile(
        "mma.sync.aligned.m16n8k16.row.col.f32.f16.f16.f32 "
        "{%0,%1,%2,%3}, {%4,%5,%6,%7}, {%8,%9}, {%0,%1,%2,%3};"
        : "+f"(c[0]), "+f"(c[1]), "+f"(c[2]), "+f"(c[3])
        : "r"(a[0]), "r"(a[1]), "r"(a[2]), "r"(a[3]), "r"(b[0]), "r"(b[1]));
}

__device__ __forceinline__ float gelu_f(float x) {
    const float c = 0.7978845608028654f;
    float x3 = x * x * x;
    return 0.5f * x * (1.0f + tanhf(c * (x + 0.044715f * x3)));
}

// ---------------------------------------------------------------------------
// Weight transpose + fp32->fp16:   wt[n][k] = half(w[k][n])
// ---------------------------------------------------------------------------
__global__ __launch_bounds__(256) void wtrans_kernel(
    const float* __restrict__ w, __half* __restrict__ wt, int K, int N)
{
    __shared__ float t[32][33];
    const int n0 = blockIdx.x * 32, k0 = blockIdx.y * 32;
    const int tx = threadIdx.x, ty = threadIdx.y;   // (32, 8)
#pragma unroll
    for (int i = 0; i < 32; i += 8)
        t[ty + i][tx] = w[(size_t)(k0 + ty + i) * N + n0 + tx];
    __syncthreads();
#pragma unroll
    for (int i = 0; i < 32; i += 8)
        wt[(size_t)(n0 + ty + i) * K + k0 + tx] = __float2half_rn(t[tx][ty + i]);
}

// ---------------------------------------------------------------------------
// LayerNorm -> fp16 out
// ---------------------------------------------------------------------------
__global__ __launch_bounds__(256) void ln_kernel(
    const float* __restrict__ x, const float* __restrict__ g,
    const float* __restrict__ b, __half* __restrict__ out)
{
    const int row = blockIdx.x;
    const int tid = threadIdx.x;
    const float* xr = x + (size_t)row * CEMB;

    float v0 = xr[tid], v1 = xr[tid + 256], v2 = xr[tid + 512];
    float s  = v0 + v1 + v2;
    float sq = v0 * v0 + v1 * v1 + v2 * v2;
#pragma unroll
    for (int o = 16; o > 0; o >>= 1) {
        s  += __shfl_xor_sync(0xffffffffu, s,  o);
        sq += __shfl_xor_sync(0xffffffffu, sq, o);
    }
    __shared__ float rs[8], rq[8];
    __shared__ float s_mu, s_rstd;
    const int wid = tid >> 5, lid = tid & 31;
    if (lid == 0) { rs[wid] = s; rq[wid] = sq; }
    __syncthreads();
    if (tid == 0) {
        float ts = 0.f, tq = 0.f;
#pragma unroll
        for (int i = 0; i < 8; i++) { ts += rs[i]; tq += rq[i]; }
        float mu  = ts * (1.0f / CEMB);
        float var = tq * (1.0f / CEMB) - mu * mu;
        s_mu = mu; s_rstd = rsqrtf(var + 1e-5f);
    }
    __syncthreads();
    const float mu = s_mu, r = s_rstd;
    __half* orow = out + (size_t)row * CEMB;
    orow[tid      ] = __float2half_rn((v0 - mu) * r * g[tid      ] + b[tid      ]);
    orow[tid + 256] = __float2half_rn((v1 - mu) * r * g[tid + 256] + b[tid + 256]);
    orow[tid + 512] = __float2half_rn((v2 - mu) * r * g[tid + 512] + b[tid + 512]);
}

// ---------------------------------------------------------------------------
// HMMA GEMM: C[M,N] = A[M,K](f16) @ Bt[N,K](f16)^T + epilogue
// BM=128 BN=128 BK=32, 256 threads (8 warps, each 64x32), cp.async double buf.
// EPI 0: outf = acc + bias
// EPI 1: outf = acc + bias + res
// EPI 2: outh = half(gelu(acc + bias))
// ---------------------------------------------------------------------------
#define BM 128
#define BN 128
#define BKK 32
#define LDS_STRIDE 40      // halves per row (32 + 8 pad) -> 80 bytes

template <int EPI>
__global__ __launch_bounds__(256) void gemm_hmma(
    int M, int N, int K,
    const __half* __restrict__ A, const __half* __restrict__ Bt,
    const float* __restrict__ bias, const float* __restrict__ res,
    float* __restrict__ outf, __half* __restrict__ outh)
{
    __shared__ __align__(16) __half sm[2][2][128 * LDS_STRIDE];

    const int tid  = threadIdx.x;
    const int lane = tid & 31, wid = tid >> 5;
    const int wr = wid >> 2, wc = wid & 3;         // warp grid 2 x 4
    const int cRow = blockIdx.y * BM, cCol = blockIdx.x * BN;

    const uint32_t sA[2] = { smem_u32(sm[0][0]), smem_u32(sm[1][0]) };
    const uint32_t sB[2] = { smem_u32(sm[0][1]), smem_u32(sm[1][1]) };

    // ---- load mapping: thread covers rows lrow and lrow+64, 8 halves each
    const int lrow = tid >> 2;          // 0..63
    const int lkc  = (tid & 3) * 8;     // 0,8,16,24
    const uint32_t soff = (uint32_t)(lrow * LDS_STRIDE + lkc) * 2;

    // ---- ldmatrix lane addressing
    const int a_row = lane & 15, koff = (lane >> 4) * 8;
    const uint32_t a_base = (uint32_t)((wr * 64 + a_row) * LDS_STRIDE + koff) * 2;
    const int b_n = (lane & 7) + ((lane >> 3) & 1) * 8;
    const uint32_t b_base = (uint32_t)((wc * 32 + b_n) * LDS_STRIDE + koff) * 2;

    float acc[4][4][4];
#pragma unroll
    for (int i = 0; i < 4; i++)
#pragma unroll
        for (int j = 0; j < 4; j++)
#pragma unroll
            for (int q = 0; q < 4; q++) acc[i][j][q] = 0.f;

    const int nK = K / BKK;

#define LOAD_TILES(kt, buf) do {                                               \
    const __half* Ag = A  + (size_t)(cRow + lrow) * K + (kt) * BKK + lkc;      \
    const __half* Bg = Bt + (size_t)(cCol + lrow) * K + (kt) * BKK + lkc;      \
    cp_async16(sA[buf] + soff,                       Ag);                      \
    cp_async16(sA[buf] + soff + 64 * LDS_STRIDE * 2, Ag + (size_t)64 * K);     \
    cp_async16(sB[buf] + soff,                       Bg);                      \
    cp_async16(sB[buf] + soff + 64 * LDS_STRIDE * 2, Bg + (size_t)64 * K);     \
} while (0)

    LOAD_TILES(0, 0);
    CP_COMMIT();

    for (int kt = 0; kt < nK; ++kt) {
        const int buf = kt & 1;
        if (kt + 1 < nK) {
            LOAD_TILES(kt + 1, buf ^ 1);
            CP_COMMIT();
            CP_WAIT(1);
        } else {
            CP_WAIT(0);
        }
        __syncthreads();

#pragma unroll
        for (int ks = 0; ks < 2; ++ks) {
            uint32_t af[4][4];
            uint32_t bf[4][2];
#pragma unroll
            for (int mi = 0; mi < 4; mi++)
                ldsm4(af[mi], sA[buf] + a_base + mi * (16 * LDS_STRIDE * 2) + ks * 32);
#pragma unroll
            for (int nj = 0; nj < 2; nj++) {
                uint32_t r[4];
                ldsm4(r, sB[buf] + b_base + nj * (16 * LDS_STRIDE * 2) + ks * 32);
                bf[nj * 2][0]     = r[0]; bf[nj * 2][1]     = r[2];
                bf[nj * 2 + 1][0] = r[1]; bf[nj * 2 + 1][1] = r[3];
            }
#pragma unroll
            for (int mi = 0; mi < 4; mi++)
#pragma unroll
                for (int ni = 0; ni < 4; ni++)
                    mma16816(acc[mi][ni], af[mi], bf[ni]);
        }
        __syncthreads();
    }
#undef LOAD_TILES

    // ---- epilogue
    const int er = lane >> 2, ec = (lane & 3) * 2;
#pragma unroll
    for (int mi = 0; mi < 4; mi++) {
        const int r0 = cRow + wr * 64 + mi * 16 + er;
#pragma unroll
        for (int ni = 0; ni < 4; ni++) {
            const int col = cCol + wc * 32 + ni * 8 + ec;
            const float b0 = bias[col], b1 = bias[col + 1];
            const float* c = acc[mi][ni];
            if (EPI == 2) {
                *(__half2*)(outh + (size_t)r0 * N + col) =
                    __floats2half2_rn(gelu_f(c[0] + b0), gelu_f(c[1] + b1));
                *(__half2*)(outh + (size_t)(r0 + 8) * N + col) =
                    __floats2half2_rn(gelu_f(c[2] + b0), gelu_f(c[3] + b1));
            } else {
                float2 v0 = make_float2(c[0] + b0, c[1] + b1);
                float2 v1 = make_float2(c[2] + b0, c[3] + b1);
                if (EPI == 1) {
                    float2 q0 = *(const float2*)(res + (size_t)r0 * N + col);
                    float2 q1 = *(const float2*)(res + (size_t)(r0 + 8) * N + col);
                    v0.x += q0.x; v0.y += q0.y; v1.x += q1.x; v1.y += q1.y;
                }
                *(float2*)(outf + (size_t)r0 * N + col)       = v0;
                *(float2*)(outf + (size_t)(r0 + 8) * N + col) = v1;
            }
        }
    }
}

// ---------------------------------------------------------------------------
// Causal attention (fp32 math), fp16 output
// ---------------------------------------------------------------------------
__global__ __launch_bounds__(128) void attn_kernel(
    const float* __restrict__ qkv, __half* __restrict__ y)
{
    __shared__ float Ks[64][64];
    __shared__ float Vs[64][64];

    const int tid   = threadIdx.x;
    const int hh    = blockIdx.y;
    const int bb    = blockIdx.z;
    const int q_idx = blockIdx.x * 128 + tid;
    const int kmax  = blockIdx.x * 128 + 127;
    const float scale = 0.125f;

    float4 qr[16];
    {
        const float* qp = qkv + ((size_t)(bb * TSEQ + q_idx)) * 2304 + hh * 64;
#pragma unroll
        for (int i = 0; i < 16; i++) qr[i] = *(const float4*)(qp + i * 4);
    }

    float m = -INFINITY, l = 0.f;
    float4 acc[16];
#pragma unroll
    for (int i = 0; i < 16; i++) acc[i] = make_float4(0.f, 0.f, 0.f, 0.f);

    const int r  = tid >> 1;
    const int cp = (tid & 1) * 32;

    for (int j0 = 0; j0 <= kmax; j0 += 64) {
        __syncthreads();
        const float* krow = qkv + ((size_t)(bb * TSEQ + j0 + r)) * 2304 + 768 + hh * 64 + cp;
        const float* vrow = krow + 768;
#pragma unroll
        for (int i = 0; i < 8; i++) {
            *(float4*)&Ks[r][cp + i * 4] = *(const float4*)(krow + i * 4);
            *(float4*)&Vs[r][cp + i * 4] = *(const float4*)(vrow + i * 4);
        }
        __syncthreads();

        const int jrem = q_idx - j0 + 1;
        if (jrem > 0) {
            const int jend = jrem < 64 ? jrem : 64;
            for (int j = 0; j < jend; j++) {
                float s = 0.f;
#pragma unroll
                for (int i = 0; i < 16; i++) {
                    float4 kv = *(float4*)&Ks[j][i * 4];
                    s += qr[i].x * kv.x + qr[i].y * kv.y
                       + qr[i].z * kv.z + qr[i].w * kv.w;
                }
                s *= scale;
                if (s > m) {
                    float f = __expf(m - s);
                    l *= f;
#pragma unroll
                    for (int i = 0; i < 16; i++) {
                        acc[i].x *= f; acc[i].y *= f;
                        acc[i].z *= f; acc[i].w *= f;
                    }
                    m = s;
                }
                float p = __expf(s - m);
                l += p;
#pragma unroll
                for (int i = 0; i < 16; i++) {
                    float4 vv = *(float4*)&Vs[j][i * 4];
                    acc[i].x += p * vv.x; acc[i].y += p * vv.y;
                    acc[i].z += p * vv.z; acc[i].w += p * vv.w;
                }
            }
        }
    }

    const float inv = 1.0f / l;
    __half* op = y + ((size_t)(bb * TSEQ + q_idx)) * CEMB + hh * 64;
#pragma unroll
    for (int i = 0; i < 16; i++) {
        float4 o = acc[i];
        *(__half2*)(op + i * 4)     = __floats2half2_rn(o.x * inv, o.y * inv);
        *(__half2*)(op + i * 4 + 2) = __floats2half2_rn(o.z * inv, o.w * inv);
    }
}

// ---------------------------------------------------------------------------
// Launch
// ---------------------------------------------------------------------------
extern "C" void kernel_launch(void* const* d_in, const int* in_sizes, int n_in,
                              void* d_out, int out_size)
{
    const float* x           = (const float*)d_in[0];
    const float* ln1_g       = (const float*)d_in[1];
    const float* ln1_b       = (const float*)d_in[2];
    const float* w_attn      = (const float*)d_in[3];
    const float* b_attn      = (const float*)d_in[4];
    const float* w_attn_proj = (const float*)d_in[5];
    const float* b_attn_proj = (const float*)d_in[6];
    const float* ln2_g       = (const float*)d_in[7];
    const float* ln2_b       = (const float*)d_in[8];
    const float* w_fc        = (const float*)d_in[9];
    const float* b_fc        = (const float*)d_in[10];
    const float* w_mlp_proj  = (const float*)d_in[11];
    const float* b_mlp_proj  = (const float*)d_in[12];
    float* out = (float*)d_out;

    __half *p_lnh, *p_atth, *p_fch, *p_wTa, *p_wTp, *p_wTf, *p_wTm;
    float *p_qkv, *p_x1;
    cudaGetSymbolAddress((void**)&p_lnh,  g_lnh);
    cudaGetSymbolAddress((void**)&p_qkv,  g_qkv);
    cudaGetSymbolAddress((void**)&p_atth, g_atth);
    cudaGetSymbolAddress((void**)&p_x1,   g_x1);
    cudaGetSymbolAddress((void**)&p_fch,  g_fch);
    cudaGetSymbolAddress((void**)&p_wTa,  g_wTa);
    cudaGetSymbolAddress((void**)&p_wTp,  g_wTp);
    cudaGetSymbolAddress((void**)&p_wTf,  g_wTf);
    cudaGetSymbolAddress((void**)&p_wTm,  g_wTm);

    const dim3 tb(32, 8);
    wtrans_kernel<<<dim3(2304 / 32,  768 / 32), tb>>>(w_attn,      p_wTa,  768, 2304);
    wtrans_kernel<<<dim3( 768 / 32,  768 / 32), tb>>>(w_attn_proj, p_wTp,  768,  768);
    wtrans_kernel<<<dim3(3072 / 32,  768 / 32), tb>>>(w_fc,        p_wTf,  768, 3072);
    wtrans_kernel<<<dim3( 768 / 32, 3072 / 32), tb>>>(w_mlp_proj,  p_wTm, 3072,  768);

    // 1. LN1 -> fp16
    ln_kernel<<<NTOK, 256>>>(x, ln1_g, ln1_b, p_lnh);

    // 2. QKV (fp32 out)
    gemm_hmma<0><<<dim3(2304 / BN, NTOK / BM), 256>>>(
        NTOK, 2304, CEMB, p_lnh, p_wTa, b_attn, nullptr, p_qkv, nullptr);

    // 3. attention -> fp16
    attn_kernel<<<dim3(TSEQ / 128, NHEAD, 2), 128>>>(p_qkv, p_atth);

    // 4. x1 = x + att @ w_attn_proj + b (fp32)
    gemm_hmma<1><<<dim3(CEMB / BN, NTOK / BM), 256>>>(
        NTOK, CEMB, CEMB, p_atth, p_wTp, b_attn_proj, x, p_x1, nullptr);

    // 5. LN2 -> fp16
    ln_kernel<<<NTOK, 256>>>(p_x1, ln2_g, ln2_b, p_lnh);

    // 6. fc = gelu(...) -> fp16
    gemm_hmma<2><<<dim3(3072 / BN, NTOK / BM), 256>>>(
        NTOK, 3072, CEMB, p_lnh, p_wTf, b_fc, nullptr, nullptr, p_fch);

    // 7. out = x1 + fc @ w_mlp_proj + b (fp32)
    gemm_hmma<1><<<dim3(CEMB / BN, NTOK / BM), 256>>>(
        NTOK, CEMB, 4 * CEMB, p_fch, p_wTm, b_mlp_proj, p_x1, out, nullptr);
}

// round 8
// speedup vs baseline: 5.9748x; 2.8905x over previous
#include <cuda_runtime.h>
#include <cuda_fp16.h>
#include <cstdint>
#include <math.h>

#define NTOK 4096          // B*T
#define CEMB 768
#define TSEQ 2048
#define NHEAD 12
#define HDIM 64

// ---------------------------------------------------------------------------
// Scratch
// ---------------------------------------------------------------------------
__device__ __half g_lnh [NTOK * CEMB];
__device__ __half g_q   [2 * NHEAD * TSEQ * HDIM];
__device__ __half g_k   [2 * NHEAD * TSEQ * HDIM];
__device__ __half g_v   [2 * NHEAD * TSEQ * HDIM];
__device__ __half g_atth[NTOK * CEMB];
__device__ float  g_x1  [NTOK * CEMB];
__device__ __half g_fch [NTOK * 4 * CEMB];
__device__ __half g_wTa [3 * CEMB * CEMB];   // [2304][768]
__device__ __half g_wTp [CEMB * CEMB];       // [768][768]
__device__ __half g_wTf [4 * CEMB * CEMB];   // [3072][768]
__device__ __half g_wTm [CEMB * 4 * CEMB];   // [768][3072]

// ---------------------------------------------------------------------------
// PTX helpers
// ---------------------------------------------------------------------------
__device__ __forceinline__ uint32_t smem_u32(const void* p) {
    uint32_t a;
    asm("{ .reg .u64 t; cvta.to.shared.u64 t, %1; cvt.u32.u64 %0, t; }"
        : "=r"(a) : "l"(p));
    return a;
}
__device__ __forceinline__ void cp_async16(uint32_t saddr, const void* g) {
    asm volatile("cp.async.cg.shared.global [%0], [%1], 16;" :: "r"(saddr), "l"(g));
}
#define CP_COMMIT() asm volatile("cp.async.commit_group;")
#define CP_WAIT(n)  asm volatile("cp.async.wait_group %0;" :: "n"(n))

__device__ __forceinline__ void ldsm4(uint32_t* r, uint32_t addr) {
    asm volatile("ldmatrix.sync.aligned.m8n8.x4.shared.b16 {%0,%1,%2,%3}, [%4];"
        : "=r"(r[0]), "=r"(r[1]), "=r"(r[2]), "=r"(r[3]) : "r"(addr));
}
__device__ __forceinline__ void ldsm4t(uint32_t* r, uint32_t addr) {
    asm volatile("ldmatrix.sync.aligned.m8n8.x4.trans.shared.b16 {%0,%1,%2,%3}, [%4];"
        : "=r"(r[0]), "=r"(r[1]), "=r"(r[2]), "=r"(r[3]) : "r"(addr));
}
__device__ __forceinline__ void mma16816(float* c, const uint32_t* a, const uint32_t* b) {
    asm volatile(
        "mma.sync.aligned.m16n8k16.row.col.f32.f16.f16.f32 "
        "{%0,%1,%2,%3}, {%4,%5,%6,%7}, {%8,%9}, {%0,%1,%2,%3};"
        : "+f"(c[0]), "+f"(c[1]), "+f"(c[2]), "+f"(c[3])
        : "r"(a[0]), "r"(a[1]), "r"(a[2]), "r"(a[3]), "r"(b[0]), "r"(b[1]));
}
__device__ __forceinline__ uint32_t f2h2(float a, float b) {
    __half2 h = __floats2half2_rn(a, b);
    return *reinterpret_cast<uint32_t*>(&h);
}

__device__ __forceinline__ float gelu_f(float x) {
    const float c = 0.7978845608028654f;
    float x3 = x * x * x;
    return 0.5f * x * (1.0f + tanhf(c * (x + 0.044715f * x3)));
}

// ---------------------------------------------------------------------------
// Weight transpose + fp32->fp16:   wt[n][k] = half(w[k][n])
// ---------------------------------------------------------------------------
__global__ __launch_bounds__(256) void wtrans_kernel(
    const float* __restrict__ w, __half* __restrict__ wt, int K, int N)
{
    __shared__ float t[32][33];
    const int n0 = blockIdx.x * 32, k0 = blockIdx.y * 32;
    const int tx = threadIdx.x, ty = threadIdx.y;   // (32, 8)
#pragma unroll
    for (int i = 0; i < 32; i += 8)
        t[ty + i][tx] = w[(size_t)(k0 + ty + i) * N + n0 + tx];
    __syncthreads();
#pragma unroll
    for (int i = 0; i < 32; i += 8)
        wt[(size_t)(n0 + ty + i) * K + k0 + tx] = __float2half_rn(t[tx][ty + i]);
}

// ---------------------------------------------------------------------------
// LayerNorm -> fp16 out
// ---------------------------------------------------------------------------
__global__ __launch_bounds__(256) void ln_kernel(
    const float* __restrict__ x, const float* __restrict__ g,
    const float* __restrict__ b, __half* __restrict__ out)
{
    const int row = blockIdx.x;
    const int tid = threadIdx.x;
    const float* xr = x + (size_t)row * CEMB;

    float v0 = xr[tid], v1 = xr[tid + 256], v2 = xr[tid + 512];
    float s  = v0 + v1 + v2;
    float sq = v0 * v0 + v1 * v1 + v2 * v2;
#pragma unroll
    for (int o = 16; o > 0; o >>= 1) {
        s  += __shfl_xor_sync(0xffffffffu, s,  o);
        sq += __shfl_xor_sync(0xffffffffu, sq, o);
    }
    __shared__ float rs[8], rq[8];
    __shared__ float s_mu, s_rstd;
    const int wid = tid >> 5, lid = tid & 31;
    if (lid == 0) { rs[wid] = s; rq[wid] = sq; }
    __syncthreads();
    if (tid == 0) {
        float ts = 0.f, tq = 0.f;
#pragma unroll
        for (int i = 0; i < 8; i++) { ts += rs[i]; tq += rq[i]; }
        float mu  = ts * (1.0f / CEMB);
        float var = tq * (1.0f / CEMB) - mu * mu;
        s_mu = mu; s_rstd = rsqrtf(var + 1e-5f);
    }
    __syncthreads();
    const float mu = s_mu, r = s_rstd;
    __half* orow = out + (size_t)row * CEMB;
    orow[tid      ] = __float2half_rn((v0 - mu) * r * g[tid      ] + b[tid      ]);
    orow[tid + 256] = __float2half_rn((v1 - mu) * r * g[tid + 256] + b[tid + 256]);
    orow[tid + 512] = __float2half_rn((v2 - mu) * r * g[tid + 512] + b[tid + 512]);
}

// ---------------------------------------------------------------------------
// HMMA GEMM: C[M,N] = A[M,K](f16) @ Bt[N,K](f16)^T + epilogue
// EPI 1: outf = acc + bias + res
// EPI 2: outh = half(gelu(acc + bias))
// EPI 3: qkv split -> qo (scaled 1/8), ko, vo in [B*H, T, 64] fp16
// ---------------------------------------------------------------------------
#define BM 128
#define BN 128
#define BKK 32
#define LDS_STRIDE 40

template <int EPI>
__global__ __launch_bounds__(256) void gemm_hmma(
    int M, int N, int K,
    const __half* __restrict__ A, const __half* __restrict__ Bt,
    const float* __restrict__ bias, const float* __restrict__ res,
    float* __restrict__ outf, __half* __restrict__ outh,
    __half* __restrict__ qo, __half* __restrict__ ko, __half* __restrict__ vo)
{
    __shared__ __align__(16) __half sm[2][2][128 * LDS_STRIDE];

    const int tid  = threadIdx.x;
    const int lane = tid & 31, wid = tid >> 5;
    const int wr = wid >> 2, wc = wid & 3;
    const int cRow = blockIdx.y * BM, cCol = blockIdx.x * BN;

    const uint32_t sA[2] = { smem_u32(sm[0][0]), smem_u32(sm[1][0]) };
    const uint32_t sB[2] = { smem_u32(sm[0][1]), smem_u32(sm[1][1]) };

    const int lrow = tid >> 2;
    const int lkc  = (tid & 3) * 8;
    const uint32_t soff = (uint32_t)(lrow * LDS_STRIDE + lkc) * 2;

    const int a_row = lane & 15, koff = (lane >> 4) * 8;
    const uint32_t a_base = (uint32_t)((wr * 64 + a_row) * LDS_STRIDE + koff) * 2;
    const int b_n = (lane & 7) + ((lane >> 3) & 1) * 8;
    const uint32_t b_base = (uint32_t)((wc * 32 + b_n) * LDS_STRIDE + koff) * 2;

    float acc[4][4][4];
#pragma unroll
    for (int i = 0; i < 4; i++)
#pragma unroll
        for (int j = 0; j < 4; j++)
#pragma unroll
            for (int q = 0; q < 4; q++) acc[i][j][q] = 0.f;

    const int nK = K / BKK;

#define LOAD_TILES(kt, buf) do {                                               \
    const __half* Ag = A  + (size_t)(cRow + lrow) * K + (kt) * BKK + lkc;      \
    const __half* Bg = Bt + (size_t)(cCol + lrow) * K + (kt) * BKK + lkc;      \
    cp_async16(sA[buf] + soff,                       Ag);                      \
    cp_async16(sA[buf] + soff + 64 * LDS_STRIDE * 2, Ag + (size_t)64 * K);     \
    cp_async16(sB[buf] + soff,                       Bg);                      \
    cp_async16(sB[buf] + soff + 64 * LDS_STRIDE * 2, Bg + (size_t)64 * K);     \
} while (0)

    LOAD_TILES(0, 0);
    CP_COMMIT();

    for (int kt = 0; kt < nK; ++kt) {
        const int buf = kt & 1;
        if (kt + 1 < nK) {
            LOAD_TILES(kt + 1, buf ^ 1);
            CP_COMMIT();
            CP_WAIT(1);
        } else {
            CP_WAIT(0);
        }
        __syncthreads();

#pragma unroll
        for (int ks = 0; ks < 2; ++ks) {
            uint32_t af[4][4];
            uint32_t bf[4][2];
#pragma unroll
            for (int mi = 0; mi < 4; mi++)
                ldsm4(af[mi], sA[buf] + a_base + mi * (16 * LDS_STRIDE * 2) + ks * 32);
#pragma unroll
            for (int nj = 0; nj < 2; nj++) {
                uint32_t r[4];
                ldsm4(r, sB[buf] + b_base + nj * (16 * LDS_STRIDE * 2) + ks * 32);
                bf[nj * 2][0]     = r[0]; bf[nj * 2][1]     = r[2];
                bf[nj * 2 + 1][0] = r[1]; bf[nj * 2 + 1][1] = r[3];
            }
#pragma unroll
            for (int mi = 0; mi < 4; mi++)
#pragma unroll
                for (int ni = 0; ni < 4; ni++)
                    mma16816(acc[mi][ni], af[mi], bf[ni]);
        }
        __syncthreads();
    }
#undef LOAD_TILES

    const int er = lane >> 2, ec = (lane & 3) * 2;
#pragma unroll
    for (int mi = 0; mi < 4; mi++) {
        const int r0 = cRow + wr * 64 + mi * 16 + er;
#pragma unroll
        for (int ni = 0; ni < 4; ni++) {
            const int col = cCol + wc * 32 + ni * 8 + ec;
            const float b0 = bias[col], b1 = bias[col + 1];
            const float* c = acc[mi][ni];
            if (EPI == 2) {
                *(__half2*)(outh + (size_t)r0 * N + col) =
                    __floats2half2_rn(gelu_f(c[0] + b0), gelu_f(c[1] + b1));
                *(__half2*)(outh + (size_t)(r0 + 8) * N + col) =
                    __floats2half2_rn(gelu_f(c[2] + b0), gelu_f(c[3] + b1));
            } else if (EPI == 3) {
                const int which = col / CEMB;
                const int rem = col - which * CEMB;
                const int hh = rem >> 6, dd = rem & 63;
                const float sc = (which == 0) ? 0.125f : 1.0f;
                __half* dst = (which == 0) ? qo : (which == 1) ? ko : vo;
#pragma unroll
                for (int half_i = 0; half_i < 2; half_i++) {
                    const int rr = r0 + half_i * 8;
                    const int bb = rr >> 11, tt = rr & 2047;
                    const size_t off = (((size_t)(bb * NHEAD + hh) * TSEQ + tt) * HDIM + dd);
                    *(__half2*)(dst + off) = __floats2half2_rn(
                        (c[half_i * 2] + b0) * sc, (c[half_i * 2 + 1] + b1) * sc);
                }
            } else {
                float2 v0 = make_float2(c[0] + b0, c[1] + b1);
                float2 v1 = make_float2(c[2] + b0, c[3] + b1);
                if (EPI == 1) {
                    float2 q0 = *(const float2*)(res + (size_t)r0 * N + col);
                    float2 q1 = *(const float2*)(res + (size_t)(r0 + 8) * N + col);
                    v0.x += q0.x; v0.y += q0.y; v1.x += q1.x; v1.y += q1.y;
                }
                *(float2*)(outf + (size_t)r0 * N + col)       = v0;
                *(float2*)(outf + (size_t)(r0 + 8) * N + col) = v1;
            }
        }
    }
}

// ---------------------------------------------------------------------------
// Flash attention (HMMA): 64 queries/CTA, 4 warps, fp16 in/out, fp32 softmax.
// Q pre-scaled by 1/8. grid = (T/64, B*H), block 128.
// ---------------------------------------------------------------------------
#define AT_ST 72   // padded halves per row

__global__ __launch_bounds__(128) void fattn_kernel(
    const __half* __restrict__ Qg, const __half* __restrict__ Kg,
    const __half* __restrict__ Vg, __half* __restrict__ y)
{
    __shared__ __align__(16) __half sQ[64 * AT_ST];
    __shared__ __align__(16) __half sK[2][64 * AT_ST];
    __shared__ __align__(16) __half sV[2][64 * AT_ST];

    const int tid = threadIdx.x, lane = tid & 31, w = tid >> 5;
    const int bh = blockIdx.y;
    const int q0 = blockIdx.x * 64;
    const size_t base = (size_t)bh * TSEQ * HDIM;
    const int nt = q0 / 64 + 1;

#define LOADKV(kt, buf) do {                                                   \
    const __half* kg = Kg + base + (size_t)(kt) * 64 * HDIM;                   \
    const __half* vg = Vg + base + (size_t)(kt) * 64 * HDIM;                   \
    _Pragma("unroll")                                                          \
    for (int i = 0; i < 4; i++) {                                              \
        const int c = tid * 4 + i;                                             \
        const int row = c >> 3, off = (c & 7) * 8;                             \
        cp_async16(smem_u32(&sK[buf][row * AT_ST + off]), kg + row * HDIM + off); \
        cp_async16(smem_u32(&sV[buf][row * AT_ST + off]), vg + row * HDIM + off); \
    }                                                                          \
} while (0)

    {
        const __half* qg = Qg + base + (size_t)q0 * HDIM;
#pragma unroll
        for (int i = 0; i < 4; i++) {
            const int c = tid * 4 + i;
            const int row = c >> 3, off = (c & 7) * 8;
            cp_async16(smem_u32(&sQ[row * AT_ST + off]), qg + row * HDIM + off);
        }
        LOADKV(0, 0);
        CP_COMMIT();
    }

    const uint32_t qbase = smem_u32(sQ) +
        (uint32_t)(((w * 16 + (lane & 15)) * AT_ST + (lane >> 4) * 8) * 2);
    const int nrow = (lane & 7) + ((lane >> 3) & 1) * 8;  // serves K(n-row) and V(k-row)
    const int coff = (lane >> 4) * 8;
    const int er = lane >> 2, ec = (lane & 3) * 2;

    float m0 = -1e30f, m1 = -1e30f, l0 = 0.f, l1 = 0.f;
    float o[8][4];
#pragma unroll
    for (int i = 0; i < 8; i++)
#pragma unroll
        for (int j = 0; j < 4; j++) o[i][j] = 0.f;

    for (int kt = 0; kt < nt; ++kt) {
        const int buf = kt & 1;
        if (kt + 1 < nt) { LOADKV(kt + 1, buf ^ 1); CP_COMMIT(); CP_WAIT(1); }
        else             { CP_WAIT(0); }
        __syncthreads();

        const uint32_t kb = smem_u32(sK[buf]);
        const uint32_t vb = smem_u32(sV[buf]);

        // ---- S = Q @ K^T  (64 keys)
        float s[8][4];
#pragma unroll
        for (int i = 0; i < 8; i++)
#pragma unroll
            for (int j = 0; j < 4; j++) s[i][j] = 0.f;

#pragma unroll
        for (int ks = 0; ks < 4; ++ks) {
            uint32_t aQ[4];
            ldsm4(aQ, qbase + ks * 32);
#pragma unroll
            for (int nj = 0; nj < 4; nj++) {
                uint32_t r[4];
                ldsm4(r, kb + (uint32_t)(((nj * 16 + nrow) * AT_ST + ks * 16 + coff) * 2));
                uint32_t bA[2] = { r[0], r[2] }, bB[2] = { r[1], r[3] };
                mma16816(s[nj * 2],     aQ, bA);
                mma16816(s[nj * 2 + 1], aQ, bB);
            }
        }

        // ---- causal mask (diagonal tile only)
        if (kt == nt - 1) {
            const int r0w = w * 16 + er, r1w = r0w + 8;
#pragma unroll
            for (int n = 0; n < 8; n++) {
                const int c0 = n * 8 + ec;
                if (c0     > r0w) s[n][0] = -1e30f;
                if (c0 + 1 > r0w) s[n][1] = -1e30f;
                if (c0     > r1w) s[n][2] = -1e30f;
                if (c0 + 1 > r1w) s[n][3] = -1e30f;
            }
        }

        // ---- online softmax
        float mx0 = -1e30f, mx1 = -1e30f;
#pragma unroll
        for (int n = 0; n < 8; n++) {
            mx0 = fmaxf(mx0, fmaxf(s[n][0], s[n][1]));
            mx1 = fmaxf(mx1, fmaxf(s[n][2], s[n][3]));
        }
        mx0 = fmaxf(mx0, __shfl_xor_sync(0xffffffffu, mx0, 1));
        mx0 = fmaxf(mx0, __shfl_xor_sync(0xffffffffu, mx0, 2));
        mx1 = fmaxf(mx1, __shfl_xor_sync(0xffffffffu, mx1, 1));
        mx1 = fmaxf(mx1, __shfl_xor_sync(0xffffffffu, mx1, 2));

        const float mn0 = fmaxf(m0, mx0), mn1 = fmaxf(m1, mx1);
        const float f0 = __expf(m0 - mn0), f1 = __expf(m1 - mn1);
        float sum0 = 0.f, sum1 = 0.f;
#pragma unroll
        for (int n = 0; n < 8; n++) {
            s[n][0] = __expf(s[n][0] - mn0); sum0 += s[n][0];
            s[n][1] = __expf(s[n][1] - mn0); sum0 += s[n][1];
            s[n][2] = __expf(s[n][2] - mn1); sum1 += s[n][2];
            s[n][3] = __expf(s[n][3] - mn1); sum1 += s[n][3];
        }
        sum0 += __shfl_xor_sync(0xffffffffu, sum0, 1);
        sum0 += __shfl_xor_sync(0xffffffffu, sum0, 2);
        sum1 += __shfl_xor_sync(0xffffffffu, sum1, 1);
        sum1 += __shfl_xor_sync(0xffffffffu, sum1, 2);
        l0 = l0 * f0 + sum0;
        l1 = l1 * f1 + sum1;
        m0 = mn0; m1 = mn1;
#pragma unroll
        for (int n = 0; n < 8; n++) {
            o[n][0] *= f0; o[n][1] *= f0;
            o[n][2] *= f1; o[n][3] *= f1;
        }

        // ---- O += P @ V
#pragma unroll
        for (int ks = 0; ks < 4; ++ks) {
            uint32_t aP[4];
            aP[0] = f2h2(s[ks * 2][0],     s[ks * 2][1]);
            aP[1] = f2h2(s[ks * 2][2],     s[ks * 2][3]);
            aP[2] = f2h2(s[ks * 2 + 1][0], s[ks * 2 + 1][1]);
            aP[3] = f2h2(s[ks * 2 + 1][2], s[ks * 2 + 1][3]);
#pragma unroll
            for (int ng = 0; ng < 4; ng++) {
                uint32_t r[4];
                ldsm4t(r, vb + (uint32_t)(((ks * 16 + nrow) * AT_ST + ng * 16 + coff) * 2));
                uint32_t bA[2] = { r[0], r[1] }, bB[2] = { r[2], r[3] };
                mma16816(o[ng * 2],     aP, bA);
                mma16816(o[ng * 2 + 1], aP, bB);
            }
        }
        __syncthreads();
    }
#undef LOADKV

    const float inv0 = 1.0f / l0, inv1 = 1.0f / l1;
    const int b = bh / NHEAD, h = bh - b * NHEAD;
    const int row0 = q0 + w * 16 + er;
    __half* yp = y + ((size_t)b * TSEQ + row0) * CEMB + h * HDIM;
#pragma unroll
    for (int ng = 0; ng < 8; ng++) {
        const int col = ng * 8 + ec;
        *(__half2*)(yp + col) = __floats2half2_rn(o[ng][0] * inv0, o[ng][1] * inv0);
        *(__half2*)(yp + (size_t)8 * CEMB + col) =
            __floats2half2_rn(o[ng][2] * inv1, o[ng][3] * inv1);
    }
}

// ---------------------------------------------------------------------------
// Launch
// ---------------------------------------------------------------------------
extern "C" void kernel_launch(void* const* d_in, const int* in_sizes, int n_in,
                              void* d_out, int out_size)
{
    const float* x           = (const float*)d_in[0];
    const float* ln1_g       = (const float*)d_in[1];
    const float* ln1_b       = (const float*)d_in[2];
    const float* w_attn      = (const float*)d_in[3];
    const float* b_attn      = (const float*)d_in[4];
    const float* w_attn_proj = (const float*)d_in[5];
    const float* b_attn_proj = (const float*)d_in[6];
    const float* ln2_g       = (const float*)d_in[7];
    const float* ln2_b       = (const float*)d_in[8];
    const float* w_fc        = (const float*)d_in[9];
    const float* b_fc        = (const float*)d_in[10];
    const float* w_mlp_proj  = (const float*)d_in[11];
    const float* b_mlp_proj  = (const float*)d_in[12];
    float* out = (float*)d_out;

    __half *p_lnh, *p_q, *p_k, *p_v, *p_atth, *p_fch, *p_wTa, *p_wTp, *p_wTf, *p_wTm;
    float *p_x1;
    cudaGetSymbolAddress((void**)&p_lnh,  g_lnh);
    cudaGetSymbolAddress((void**)&p_q,    g_q);
    cudaGetSymbolAddress((void**)&p_k,    g_k);
    cudaGetSymbolAddress((void**)&p_v,    g_v);
    cudaGetSymbolAddress((void**)&p_atth, g_atth);
    cudaGetSymbolAddress((void**)&p_x1,   g_x1);
    cudaGetSymbolAddress((void**)&p_fch,  g_fch);
    cudaGetSymbolAddress((void**)&p_wTa,  g_wTa);
    cudaGetSymbolAddress((void**)&p_wTp,  g_wTp);
    cudaGetSymbolAddress((void**)&p_wTf,  g_wTf);
    cudaGetSymbolAddress((void**)&p_wTm,  g_wTm);

    const dim3 tb(32, 8);
    wtrans_kernel<<<dim3(2304 / 32,  768 / 32), tb>>>(w_attn,      p_wTa,  768, 2304);
    wtrans_kernel<<<dim3( 768 / 32,  768 / 32), tb>>>(w_attn_proj, p_wTp,  768,  768);
    wtrans_kernel<<<dim3(3072 / 32,  768 / 32), tb>>>(w_fc,        p_wTf,  768, 3072);
    wtrans_kernel<<<dim3( 768 / 32, 3072 / 32), tb>>>(w_mlp_proj,  p_wTm, 3072,  768);

    // 1. LN1 -> fp16
    ln_kernel<<<NTOK, 256>>>(x, ln1_g, ln1_b, p_lnh);

    // 2. QKV -> split fp16 Q (x1/8), K, V in [B*H, T, 64]
    gemm_hmma<3><<<dim3(2304 / BN, NTOK / BM), 256>>>(
        NTOK, 2304, CEMB, p_lnh, p_wTa, b_attn, nullptr, nullptr, nullptr,
        p_q, p_k, p_v);

    // 3. flash attention -> fp16 [token][C]
    fattn_kernel<<<dim3(TSEQ / 64, 2 * NHEAD), 128>>>(p_q, p_k, p_v, p_atth);

    // 4. x1 = x + att @ w_attn_proj + b (fp32)
    gemm_hmma<1><<<dim3(CEMB / BN, NTOK / BM), 256>>>(
        NTOK, CEMB, CEMB, p_atth, p_wTp, b_attn_proj, x, p_x1, nullptr,
        nullptr, nullptr, nullptr);

    // 5. LN2 -> fp16
    ln_kernel<<<NTOK, 256>>>(p_x1, ln2_g, ln2_b, p_lnh);

    // 6. fc = gelu(...) -> fp16
    gemm_hmma<2><<<dim3(3072 / BN, NTOK / BM), 256>>>(
        NTOK, 3072, CEMB, p_lnh, p_wTf, b_fc, nullptr, nullptr, p_fch,
        nullptr, nullptr, nullptr);

    // 7. out = x1 + fc @ w_mlp_proj + b (fp32)
    gemm_hmma<1><<<dim3(CEMB / BN, NTOK / BM), 256>>>(
        NTOK, CEMB, 4 * CEMB, p_fch, p_wTm, b_mlp_proj, p_x1, out, nullptr,
        nullptr, nullptr, nullptr);
}

// round 10
// speedup vs baseline: 6.4260x; 1.0755x over previous
#include <cuda_runtime.h>
#include <cuda_fp16.h>
#include <cstdint>
#include <math.h>

#define NTOK 4096          // B*T
#define CEMB 768
#define TSEQ 2048
#define NHEAD 12
#define HDIM 64

// ---------------------------------------------------------------------------
// Scratch
// ---------------------------------------------------------------------------
__device__ __half g_lnh [NTOK * CEMB];
__device__ __half g_q   [2 * NHEAD * TSEQ * HDIM];
__device__ __half g_k   [2 * NHEAD * TSEQ * HDIM];
__device__ __half g_v   [2 * NHEAD * TSEQ * HDIM];
__device__ __half g_atth[NTOK * CEMB];
__device__ float  g_x1  [NTOK * CEMB];
__device__ __half g_fch [NTOK * 4 * CEMB];
__device__ __half g_wTa [3 * CEMB * CEMB];   // [2304][768]
__device__ __half g_wTp [CEMB * CEMB];       // [768][768]
__device__ __half g_wTf [4 * CEMB * CEMB];   // [3072][768]
__device__ __half g_wTm [CEMB * 4 * CEMB];   // [768][3072]

// ---------------------------------------------------------------------------
// PTX helpers
// ---------------------------------------------------------------------------
__device__ __forceinline__ uint32_t smem_u32(const void* p) {
    uint32_t a;
    asm("{ .reg .u64 t; cvta.to.shared.u64 t, %1; cvt.u32.u64 %0, t; }"
        : "=r"(a) : "l"(p));
    return a;
}
__device__ __forceinline__ void cp_async16(uint32_t saddr, const void* g) {
    asm volatile("cp.async.cg.shared.global [%0], [%1], 16;" :: "r"(saddr), "l"(g));
}
#define CP_COMMIT() asm volatile("cp.async.commit_group;")
#define CP_WAIT(n)  asm volatile("cp.async.wait_group %0;" :: "n"(n))

__device__ __forceinline__ void ldsm4(uint32_t* r, uint32_t addr) {
    asm volatile("ldmatrix.sync.aligned.m8n8.x4.shared.b16 {%0,%1,%2,%3}, [%4];"
        : "=r"(r[0]), "=r"(r[1]), "=r"(r[2]), "=r"(r[3]) : "r"(addr));
}
__device__ __forceinline__ void ldsm4t(uint32_t* r, uint32_t addr) {
    asm volatile("ldmatrix.sync.aligned.m8n8.x4.trans.shared.b16 {%0,%1,%2,%3}, [%4];"
        : "=r"(r[0]), "=r"(r[1]), "=r"(r[2]), "=r"(r[3]) : "r"(addr));
}
__device__ __forceinline__ void mma16816(float* c, const uint32_t* a, const uint32_t* b) {
    asm volatile(
        "mma.sync.aligned.m16n8k16.row.col.f32.f16.f16.f32 "
        "{%0,%1,%2,%3}, {%4,%5,%6,%7}, {%8,%9}, {%0,%1,%2,%3};"
        : "+f"(c[0]), "+f"(c[1]), "+f"(c[2]), "+f"(c[3])
        : "r"(a[0]), "r"(a[1]), "r"(a[2]), "r"(a[3]), "r"(b[0]), "r"(b[1]));
}
__device__ __forceinline__ uint32_t f2h2(float a, float b) {
    __half2 h = __floats2half2_rn(a, b);
    return *reinterpret_cast<uint32_t*>(&h);
}

__device__ __forceinline__ float gelu_f(float x) {
    const float c = 0.7978845608028654f;
    float x3 = x * x * x;
    return 0.5f * x * (1.0f + tanhf(c * (x + 0.044715f * x3)));
}

// ---------------------------------------------------------------------------
// Weight transpose + fp32->fp16:   wt[n][k] = half(w[k][n])
// ---------------------------------------------------------------------------
__global__ __launch_bounds__(256) void wtrans_kernel(
    const float* __restrict__ w, __half* __restrict__ wt, int K, int N)
{
    __shared__ float t[32][33];
    const int n0 = blockIdx.x * 32, k0 = blockIdx.y * 32;
    const int tx = threadIdx.x, ty = threadIdx.y;   // (32, 8)
#pragma unroll
    for (int i = 0; i < 32; i += 8)
        t[ty + i][tx] = w[(size_t)(k0 + ty + i) * N + n0 + tx];
    __syncthreads();
#pragma unroll
    for (int i = 0; i < 32; i += 8)
        wt[(size_t)(n0 + ty + i) * K + k0 + tx] = __float2half_rn(t[tx][ty + i]);
}

// ---------------------------------------------------------------------------
// LayerNorm -> fp16 out
// ---------------------------------------------------------------------------
__global__ __launch_bounds__(256) void ln_kernel(
    const float* __restrict__ x, const float* __restrict__ g,
    const float* __restrict__ b, __half* __restrict__ out)
{
    const int row = blockIdx.x;
    const int tid = threadIdx.x;
    const float* xr = x + (size_t)row * CEMB;

    float v0 = xr[tid], v1 = xr[tid + 256], v2 = xr[tid + 512];
    float s  = v0 + v1 + v2;
    float sq = v0 * v0 + v1 * v1 + v2 * v2;
#pragma unroll
    for (int o = 16; o > 0; o >>= 1) {
        s  += __shfl_xor_sync(0xffffffffu, s,  o);
        sq += __shfl_xor_sync(0xffffffffu, sq, o);
    }
    __shared__ float rs[8], rq[8];
    __shared__ float s_mu, s_rstd;
    const int wid = tid >> 5, lid = tid & 31;
    if (lid == 0) { rs[wid] = s; rq[wid] = sq; }
    __syncthreads();
    if (tid == 0) {
        float ts = 0.f, tq = 0.f;
#pragma unroll
        for (int i = 0; i < 8; i++) { ts += rs[i]; tq += rq[i]; }
        float mu  = ts * (1.0f / CEMB);
        float var = tq * (1.0f / CEMB) - mu * mu;
        s_mu = mu; s_rstd = rsqrtf(var + 1e-5f);
    }
    __syncthreads();
    const float mu = s_mu, r = s_rstd;
    __half* orow = out + (size_t)row * CEMB;
    orow[tid      ] = __float2half_rn((v0 - mu) * r * g[tid      ] + b[tid      ]);
    orow[tid + 256] = __float2half_rn((v1 - mu) * r * g[tid + 256] + b[tid + 256]);
    orow[tid + 512] = __float2half_rn((v2 - mu) * r * g[tid + 512] + b[tid + 512]);
}

// ---------------------------------------------------------------------------
// HMMA GEMM: C[M,N] = A[M,K](f16) @ Bt[N,K](f16)^T + epilogue
// BM=128 BN=128 BK=64, 256 threads (8 warps, each 64x32), cp.async double buf,
// ONE __syncthreads per mainloop iteration.
// EPI 1: outf = acc + bias + res
// EPI 2: outh = half(gelu(acc + bias))
// EPI 3: qkv split -> qo (scaled 1/8), ko, vo in [B*H, T, 64] fp16
// ---------------------------------------------------------------------------
#define BM 128
#define BN 128
#define BKK 64
#define LDS_STRIDE 72                       // halves per row (64 + 8 pad)
#define GT_HALVES (128 * LDS_STRIDE)        // halves per tile
static constexpr int GEMM_SMEM = 4 * GT_HALVES * 2;   // 73728 B

template <int EPI>
__global__ __launch_bounds__(256) void gemm_hmma(
    int M, int N, int K,
    const __half* __restrict__ A, const __half* __restrict__ Bt,
    const float* __restrict__ bias, const float* __restrict__ res,
    float* __restrict__ outf, __half* __restrict__ outh,
    __half* __restrict__ qo, __half* __restrict__ ko, __half* __restrict__ vo)
{
    extern __shared__ __align__(16) __half dynsm[];

    const int tid  = threadIdx.x;
    const int lane = tid & 31, wid = tid >> 5;
    const int wr = wid >> 2, wc = wid & 3;
    const int cRow = blockIdx.y * BM, cCol = blockIdx.x * BN;

    // layout: [buf][A|B] tiles of GT_HALVES halves
    const uint32_t sA[2] = { smem_u32(dynsm),
                             smem_u32(dynsm + 2 * GT_HALVES) };
    const uint32_t sB[2] = { smem_u32(dynsm + GT_HALVES),
                             smem_u32(dynsm + 3 * GT_HALVES) };

    const int a_row = lane & 15, koff = (lane >> 4) * 8;
    const uint32_t a_base = (uint32_t)((wr * 64 + a_row) * LDS_STRIDE + koff) * 2;
    const int b_n = (lane & 7) + ((lane >> 3) & 1) * 8;
    const uint32_t b_base = (uint32_t)((wc * 32 + b_n) * LDS_STRIDE + koff) * 2;

    float acc[4][4][4];
#pragma unroll
    for (int i = 0; i < 4; i++)
#pragma unroll
        for (int j = 0; j < 4; j++)
#pragma unroll
            for (int q = 0; q < 4; q++) acc[i][j][q] = 0.f;

    const int nK = K / BKK;

#define LOAD_TILES(kt, buf) do {                                               \
    const __half* Ag = A  + (size_t)cRow * K + (kt) * BKK;                     \
    const __half* Bg = Bt + (size_t)cCol * K + (kt) * BKK;                     \
    const uint32_t sa = sA[buf], sb = sB[buf];                                 \
    _Pragma("unroll")                                                          \
    for (int i = 0; i < 4; i++) {                                              \
        const int c = i * 256 + tid;                                           \
        const int row = c >> 3, off = (c & 7) * 8;                             \
        const uint32_t so = (uint32_t)(row * LDS_STRIDE + off) * 2;            \
        cp_async16(sa + so, Ag + (size_t)row * K + off);                       \
        cp_async16(sb + so, Bg + (size_t)row * K + off);                       \
    }                                                                          \
} while (0)

    LOAD_TILES(0, 0);
    CP_COMMIT();

    for (int kt = 0; kt < nK; ++kt) {
        const int buf = kt & 1;
        CP_WAIT(0);
        __syncthreads();
        if (kt + 1 < nK) {
            LOAD_TILES(kt + 1, buf ^ 1);
            CP_COMMIT();
        }
#pragma unroll
        for (int ks = 0; ks < 4; ++ks) {
            uint32_t af[4][4];
            uint32_t bf[4][2];
#pragma unroll
            for (int mi = 0; mi < 4; mi++)
                ldsm4(af[mi], sA[buf] + a_base + mi * (16 * LDS_STRIDE * 2) + ks * 32);
#pragma unroll
            for (int nj = 0; nj < 2; nj++) {
                uint32_t r[4];
                ldsm4(r, sB[buf] + b_base + nj * (16 * LDS_STRIDE * 2) + ks * 32);
                bf[nj * 2][0]     = r[0]; bf[nj * 2][1]     = r[2];
                bf[nj * 2 + 1][0] = r[1]; bf[nj * 2 + 1][1] = r[3];
            }
#pragma unroll
            for (int mi = 0; mi < 4; mi++)
#pragma unroll
                for (int ni = 0; ni < 4; ni++)
                    mma16816(acc[mi][ni], af[mi], bf[ni]);
        }
    }
#undef LOAD_TILES

    const int er = lane >> 2, ec = (lane & 3) * 2;
#pragma unroll
    for (int mi = 0; mi < 4; mi++) {
        const int r0 = cRow + wr * 64 + mi * 16 + er;
#pragma unroll
        for (int ni = 0; ni < 4; ni++) {
            const int col = cCol + wc * 32 + ni * 8 + ec;
            const float b0 = bias[col], b1 = bias[col + 1];
            const float* c = acc[mi][ni];
            if (EPI == 2) {
                *(__half2*)(outh + (size_t)r0 * N + col) =
                    __floats2half2_rn(gelu_f(c[0] + b0), gelu_f(c[1] + b1));
                *(__half2*)(outh + (size_t)(r0 + 8) * N + col) =
                    __floats2half2_rn(gelu_f(c[2] + b0), gelu_f(c[3] + b1));
            } else if (EPI == 3) {
                const int which = col / CEMB;
                const int rem = col - which * CEMB;
                const int hh = rem >> 6, dd = rem & 63;
                const float sc = (which == 0) ? 0.125f : 1.0f;
                __half* dst = (which == 0) ? qo : (which == 1) ? ko : vo;
#pragma unroll
                for (int half_i = 0; half_i < 2; half_i++) {
                    const int rr = r0 + half_i * 8;
                    const int bb = rr >> 11, tt = rr & 2047;
                    const size_t off = (((size_t)(bb * NHEAD + hh) * TSEQ + tt) * HDIM + dd);
                    *(__half2*)(dst + off) = __floats2half2_rn(
                        (c[half_i * 2] + b0) * sc, (c[half_i * 2 + 1] + b1) * sc);
                }
            } else {
                float2 v0 = make_float2(c[0] + b0, c[1] + b1);
                float2 v1 = make_float2(c[2] + b0, c[3] + b1);
                if (EPI == 1) {
                    float2 q0 = *(const float2*)(res + (size_t)r0 * N + col);
                    float2 q1 = *(const float2*)(res + (size_t)(r0 + 8) * N + col);
                    v0.x += q0.x; v0.y += q0.y; v1.x += q1.x; v1.y += q1.y;
                }
                *(float2*)(outf + (size_t)r0 * N + col)       = v0;
                *(float2*)(outf + (size_t)(r0 + 8) * N + col) = v1;
            }
        }
    }
}

// ---------------------------------------------------------------------------
// Flash attention (HMMA): 64 queries/CTA, 4 warps, fp16 in/out, fp32 softmax.
// Q pre-scaled by 1/8. grid = (T/64, B*H), block 128.
// ---------------------------------------------------------------------------
#define AT_ST 72   // padded halves per row

__global__ __launch_bounds__(128) void fattn_kernel(
    const __half* __restrict__ Qg, const __half* __restrict__ Kg,
    const __half* __restrict__ Vg, __half* __restrict__ y)
{
    __shared__ __align__(16) __half sQ[64 * AT_ST];
    __shared__ __align__(16) __half sK[2][64 * AT_ST];
    __shared__ __align__(16) __half sV[2][64 * AT_ST];

    const int tid = threadIdx.x, lane = tid & 31, w = tid >> 5;
    const int bh = blockIdx.y;
    const int q0 = blockIdx.x * 64;
    const size_t base = (size_t)bh * TSEQ * HDIM;
    const int nt = q0 / 64 + 1;

#define LOADKV(kt, buf) do {                                                   \
    const __half* kg = Kg + base + (size_t)(kt) * 64 * HDIM;                   \
    const __half* vg = Vg + base + (size_t)(kt) * 64 * HDIM;                   \
    _Pragma("unroll")                                                          \
    for (int i = 0; i < 4; i++) {                                              \
        const int c = tid * 4 + i;                                             \
        const int row = c >> 3, off = (c & 7) * 8;                             \
        cp_async16(smem_u32(&sK[buf][row * AT_ST + off]), kg + row * HDIM + off); \
        cp_async16(smem_u32(&sV[buf][row * AT_ST + off]), vg + row * HDIM + off); \
    }                                                                          \
} while (0)

    {
        const __half* qg = Qg + base + (size_t)q0 * HDIM;
#pragma unroll
        for (int i = 0; i < 4; i++) {
            const int c = tid * 4 + i;
            const int row = c >> 3, off = (c & 7) * 8;
            cp_async16(smem_u32(&sQ[row * AT_ST + off]), qg + row * HDIM + off);
        }
        LOADKV(0, 0);
        CP_COMMIT();
    }

    const uint32_t qbase = smem_u32(sQ) +
        (uint32_t)(((w * 16 + (lane & 15)) * AT_ST + (lane >> 4) * 8) * 2);
    const int nrow = (lane & 7) + ((lane >> 3) & 1) * 8;
    const int coff = (lane >> 4) * 8;
    const int er = lane >> 2, ec = (lane & 3) * 2;

    float m0 = -1e30f, m1 = -1e30f, l0 = 0.f, l1 = 0.f;
    float o[8][4];
#pragma unroll
    for (int i = 0; i < 8; i++)
#pragma unroll
        for (int j = 0; j < 4; j++) o[i][j] = 0.f;

    for (int kt = 0; kt < nt; ++kt) {
        const int buf = kt & 1;
        if (kt + 1 < nt) { LOADKV(kt + 1, buf ^ 1); CP_COMMIT(); CP_WAIT(1); }
        else             { CP_WAIT(0); }
        __syncthreads();

        const uint32_t kb = smem_u32(sK[buf]);
        const uint32_t vb = smem_u32(sV[buf]);

        // ---- S = Q @ K^T  (64 keys)
        float s[8][4];
#pragma unroll
        for (int i = 0; i < 8; i++)
#pragma unroll
            for (int j = 0; j < 4; j++) s[i][j] = 0.f;

#pragma unroll
        for (int ks = 0; ks < 4; ++ks) {
            uint32_t aQ[4];
            ldsm4(aQ, qbase + ks * 32);
#pragma unroll
            for (int nj = 0; nj < 4; nj++) {
                uint32_t r[4];
                ldsm4(r, kb + (uint32_t)(((nj * 16 + nrow) * AT_ST + ks * 16 + coff) * 2));
                uint32_t bA[2] = { r[0], r[2] }, bB[2] = { r[1], r[3] };
                mma16816(s[nj * 2],     aQ, bA);
                mma16816(s[nj * 2 + 1], aQ, bB);
            }
        }

        // ---- causal mask (diagonal tile only)
        if (kt == nt - 1) {
            const int r0w = w * 16 + er, r1w = r0w + 8;
#pragma unroll
            for (int n = 0; n < 8; n++) {
                const int c0 = n * 8 + ec;
                if (c0     > r0w) s[n][0] = -1e30f;
                if (c0 + 1 > r0w) s[n][1] = -1e30f;
                if (c0     > r1w) s[n][2] = -1e30f;
                if (c0 + 1 > r1w) s[n][3] = -1e30f;
            }
        }

        // ---- online softmax
        float mx0 = -1e30f, mx1 = -1e30f;
#pragma unroll
        for (int n = 0; n < 8; n++) {
            mx0 = fmaxf(mx0, fmaxf(s[n][0], s[n][1]));
            mx1 = fmaxf(mx1, fmaxf(s[n][2], s[n][3]));
        }
        mx0 = fmaxf(mx0, __shfl_xor_sync(0xffffffffu, mx0, 1));
        mx0 = fmaxf(mx0, __shfl_xor_sync(0xffffffffu, mx0, 2));
        mx1 = fmaxf(mx1, __shfl_xor_sync(0xffffffffu, mx1, 1));
        mx1 = fmaxf(mx1, __shfl_xor_sync(0xffffffffu, mx1, 2));

        const float mn0 = fmaxf(m0, mx0), mn1 = fmaxf(m1, mx1);
        const float f0 = __expf(m0 - mn0), f1 = __expf(m1 - mn1);
        float sum0 = 0.f, sum1 = 0.f;
#pragma unroll
        for (int n = 0; n < 8; n++) {
            s[n][0] = __expf(s[n][0] - mn0); sum0 += s[n][0];
            s[n][1] = __expf(s[n][1] - mn0); sum0 += s[n][1];
            s[n][2] = __expf(s[n][2] - mn1); sum1 += s[n][2];
            s[n][3] = __expf(s[n][3] - mn1); sum1 += s[n][3];
        }
        sum0 += __shfl_xor_sync(0xffffffffu, sum0, 1);
        sum0 += __shfl_xor_sync(0xffffffffu, sum0, 2);
        sum1 += __shfl_xor_sync(0xffffffffu, sum1, 1);
        sum1 += __shfl_xor_sync(0xffffffffu, sum1, 2);
        l0 = l0 * f0 + sum0;
        l1 = l1 * f1 + sum1;
        m0 = mn0; m1 = mn1;
#pragma unroll
        for (int n = 0; n < 8; n++) {
            o[n][0] *= f0; o[n][1] *= f0;
            o[n][2] *= f1; o[n][3] *= f1;
        }

        // ---- O += P @ V
#pragma unroll
        for (int ks = 0; ks < 4; ++ks) {
            uint32_t aP[4];
            aP[0] = f2h2(s[ks * 2][0],     s[ks * 2][1]);
            aP[1] = f2h2(s[ks * 2][2],     s[ks * 2][3]);
            aP[2] = f2h2(s[ks * 2 + 1][0], s[ks * 2 + 1][1]);
            aP[3] = f2h2(s[ks * 2 + 1][2], s[ks * 2 + 1][3]);
#pragma unroll
            for (int ng = 0; ng < 4; ng++) {
                uint32_t r[4];
                ldsm4t(r, vb + (uint32_t)(((ks * 16 + nrow) * AT_ST + ng * 16 + coff) * 2));
                uint32_t bA[2] = { r[0], r[1] }, bB[2] = { r[2], r[3] };
                mma16816(o[ng * 2],     aP, bA);
                mma16816(o[ng * 2 + 1], aP, bB);
            }
        }
        __syncthreads();
    }
#undef LOADKV

    const float inv0 = 1.0f / l0, inv1 = 1.0f / l1;
    const int b = bh / NHEAD, h = bh - b * NHEAD;
    const int row0 = q0 + w * 16 + er;
    __half* yp = y + ((size_t)b * TSEQ + row0) * CEMB + h * HDIM;
#pragma unroll
    for (int ng = 0; ng < 8; ng++) {
        const int col = ng * 8 + ec;
        *(__half2*)(yp + col) = __floats2half2_rn(o[ng][0] * inv0, o[ng][1] * inv0);
        *(__half2*)(yp + (size_t)8 * CEMB + col) =
            __floats2half2_rn(o[ng][2] * inv1, o[ng][3] * inv1);
    }
}

// ---------------------------------------------------------------------------
// Launch
// ---------------------------------------------------------------------------
extern "C" void kernel_launch(void* const* d_in, const int* in_sizes, int n_in,
                              void* d_out, int out_size)
{
    const float* x           = (const float*)d_in[0];
    const float* ln1_g       = (const float*)d_in[1];
    const float* ln1_b       = (const float*)d_in[2];
    const float* w_attn      = (const float*)d_in[3];
    const float* b_attn      = (const float*)d_in[4];
    const float* w_attn_proj = (const float*)d_in[5];
    const float* b_attn_proj = (const float*)d_in[6];
    const float* ln2_g       = (const float*)d_in[7];
    const float* ln2_b       = (const float*)d_in[8];
    const float* w_fc        = (const float*)d_in[9];
    const float* b_fc        = (const float*)d_in[10];
    const float* w_mlp_proj  = (const float*)d_in[11];
    const float* b_mlp_proj  = (const float*)d_in[12];
    float* out = (float*)d_out;

    __half *p_lnh, *p_q, *p_k, *p_v, *p_atth, *p_fch, *p_wTa, *p_wTp, *p_wTf, *p_wTm;
    float *p_x1;
    cudaGetSymbolAddress((void**)&p_lnh,  g_lnh);
    cudaGetSymbolAddress((void**)&p_q,    g_q);
    cudaGetSymbolAddress((void**)&p_k,    g_k);
    cudaGetSymbolAddress((void**)&p_v,    g_v);
    cudaGetSymbolAddress((void**)&p_atth, g_atth);
    cudaGetSymbolAddress((void**)&p_x1,   g_x1);
    cudaGetSymbolAddress((void**)&p_fch,  g_fch);
    cudaGetSymbolAddress((void**)&p_wTa,  g_wTa);
    cudaGetSymbolAddress((void**)&p_wTp,  g_wTp);
    cudaGetSymbolAddress((void**)&p_wTf,  g_wTf);
    cudaGetSymbolAddress((void**)&p_wTm,  g_wTm);

    cudaFuncSetAttribute(gemm_hmma<1>, cudaFuncAttributeMaxDynamicSharedMemorySize, GEMM_SMEM);
    cudaFuncSetAttribute(gemm_hmma<2>, cudaFuncAttributeMaxDynamicSharedMemorySize, GEMM_SMEM);
    cudaFuncSetAttribute(gemm_hmma<3>, cudaFuncAttributeMaxDynamicSharedMemorySize, GEMM_SMEM);

    const dim3 tb(32, 8);
    wtrans_kernel<<<dim3(2304 / 32,  768 / 32), tb>>>(w_attn,      p_wTa,  768, 2304);
    wtrans_kernel<<<dim3( 768 / 32,  768 / 32), tb>>>(w_attn_proj, p_wTp,  768,  768);
    wtrans_kernel<<<dim3(3072 / 32,  768 / 32), tb>>>(w_fc,        p_wTf,  768, 3072);
    wtrans_kernel<<<dim3( 768 / 32, 3072 / 32), tb>>>(w_mlp_proj,  p_wTm, 3072,  768);

    // 1. LN1 -> fp16
    ln_kernel<<<NTOK, 256>>>(x, ln1_g, ln1_b, p_lnh);

    // 2. QKV -> split fp16 Q (x1/8), K, V in [B*H, T, 64]
    gemm_hmma<3><<<dim3(2304 / BN, NTOK / BM), 256, GEMM_SMEM>>>(
        NTOK, 2304, CEMB, p_lnh, p_wTa, b_attn, nullptr, nullptr, nullptr,
        p_q, p_k, p_v);

    // 3. flash attention -> fp16 [token][C]
    fattn_kernel<<<dim3(TSEQ / 64, 2 * NHEAD), 128>>>(p_q, p_k, p_v, p_atth);

    // 4. x1 = x + att @ w_attn_proj + b (fp32)
    gemm_hmma<1><<<dim3(CEMB / BN, NTOK / BM), 256, GEMM_SMEM>>>(
        NTOK, CEMB, CEMB, p_atth, p_wTp, b_attn_proj, x, p_x1, nullptr,
        nullptr, nullptr, nullptr);

    // 5. LN2 -> fp16
    ln_kernel<<<NTOK, 256>>>(p_x1, ln2_g, ln2_b, p_lnh);

    // 6. fc = gelu(...) -> fp16
    gemm_hmma<2><<<dim3(3072 / BN, NTOK / BM), 256, GEMM_SMEM>>>(
        NTOK, 3072, CEMB, p_lnh, p_wTf, b_fc, nullptr, nullptr, p_fch,
        nullptr, nullptr, nullptr);

    // 7. out = x1 + fc @ w_mlp_proj + b (fp32)
    gemm_hmma<1><<<dim3(CEMB / BN, NTOK / BM), 256, GEMM_SMEM>>>(
        NTOK, CEMB, 4 * CEMB, p_fch, p_wTm, b_mlp_proj, p_x1, out, nullptr,
        nullptr, nullptr, nullptr);
}

// round 11
// speedup vs baseline: 7.0565x; 1.0981x over previous
#include <cuda_runtime.h>
#include <cuda_fp16.h>
#include <cstdint>
#include <math.h>

#define NTOK 4096          // B*T
#define CEMB 768
#define TSEQ 2048
#define NHEAD 12
#define HDIM 64

// ---------------------------------------------------------------------------
// Scratch
// ---------------------------------------------------------------------------
__device__ __half g_lnh [NTOK * CEMB];
__device__ __half g_q   [2 * NHEAD * TSEQ * HDIM];
__device__ __half g_k   [2 * NHEAD * TSEQ * HDIM];
__device__ __half g_v   [2 * NHEAD * TSEQ * HDIM];
__device__ __half g_atth[NTOK * CEMB];
__device__ float  g_x1  [NTOK * CEMB];
__device__ __half g_fch [NTOK * 4 * CEMB];
__device__ __half g_wTa [3 * CEMB * CEMB];   // [2304][768]
__device__ __half g_wTp [CEMB * CEMB];       // [768][768]
__device__ __half g_wTf [4 * CEMB * CEMB];   // [3072][768]
__device__ __half g_wTm [CEMB * 4 * CEMB];   // [768][3072]

// ---------------------------------------------------------------------------
// PTX helpers
// ---------------------------------------------------------------------------
__device__ __forceinline__ uint32_t smem_u32(const void* p) {
    uint32_t a;
    asm("{ .reg .u64 t; cvta.to.shared.u64 t, %1; cvt.u32.u64 %0, t; }"
        : "=r"(a) : "l"(p));
    return a;
}
__device__ __forceinline__ void cp_async16(uint32_t saddr, const void* g) {
    asm volatile("cp.async.cg.shared.global [%0], [%1], 16;" :: "r"(saddr), "l"(g));
}
#define CP_COMMIT() asm volatile("cp.async.commit_group;")
#define CP_WAIT(n)  asm volatile("cp.async.wait_group %0;" :: "n"(n))

__device__ __forceinline__ void ldsm4(uint32_t* r, uint32_t addr) {
    asm volatile("ldmatrix.sync.aligned.m8n8.x4.shared.b16 {%0,%1,%2,%3}, [%4];"
        : "=r"(r[0]), "=r"(r[1]), "=r"(r[2]), "=r"(r[3]) : "r"(addr));
}
__device__ __forceinline__ void ldsm4t(uint32_t* r, uint32_t addr) {
    asm volatile("ldmatrix.sync.aligned.m8n8.x4.trans.shared.b16 {%0,%1,%2,%3}, [%4];"
        : "=r"(r[0]), "=r"(r[1]), "=r"(r[2]), "=r"(r[3]) : "r"(addr));
}
__device__ __forceinline__ void mma16816(float* c, const uint32_t* a, const uint32_t* b) {
    asm volatile(
        "mma.sync.aligned.m16n8k16.row.col.f32.f16.f16.f32 "
        "{%0,%1,%2,%3}, {%4,%5,%6,%7}, {%8,%9}, {%0,%1,%2,%3};"
        : "+f"(c[0]), "+f"(c[1]), "+f"(c[2]), "+f"(c[3])
        : "r"(a[0]), "r"(a[1]), "r"(a[2]), "r"(a[3]), "r"(b[0]), "r"(b[1]));
}
__device__ __forceinline__ uint32_t f2h2(float a, float b) {
    __half2 h = __floats2half2_rn(a, b);
    return *reinterpret_cast<uint32_t*>(&h);
}

__device__ __forceinline__ float gelu_f(float x) {
    const float c = 0.7978845608028654f;
    float x3 = x * x * x;
    return 0.5f * x * (1.0f + tanhf(c * (x + 0.044715f * x3)));
}

// ---------------------------------------------------------------------------
// Weight transpose + fp32->fp16:   wt[n][k] = half(w[k][n])
// ---------------------------------------------------------------------------
__global__ __launch_bounds__(256) void wtrans_kernel(
    const float* __restrict__ w, __half* __restrict__ wt, int K, int N)
{
    __shared__ float t[32][33];
    const int n0 = blockIdx.x * 32, k0 = blockIdx.y * 32;
    const int tx = threadIdx.x, ty = threadIdx.y;   // (32, 8)
#pragma unroll
    for (int i = 0; i < 32; i += 8)
        t[ty + i][tx] = w[(size_t)(k0 + ty + i) * N + n0 + tx];
    __syncthreads();
#pragma unroll
    for (int i = 0; i < 32; i += 8)
        wt[(size_t)(n0 + ty + i) * K + k0 + tx] = __float2half_rn(t[tx][ty + i]);
}

// ---------------------------------------------------------------------------
// LayerNorm -> fp16 out
// ---------------------------------------------------------------------------
__global__ __launch_bounds__(256) void ln_kernel(
    const float* __restrict__ x, const float* __restrict__ g,
    const float* __restrict__ b, __half* __restrict__ out)
{
    const int row = blockIdx.x;
    const int tid = threadIdx.x;
    const float* xr = x + (size_t)row * CEMB;

    float v0 = xr[tid], v1 = xr[tid + 256], v2 = xr[tid + 512];
    float s  = v0 + v1 + v2;
    float sq = v0 * v0 + v1 * v1 + v2 * v2;
#pragma unroll
    for (int o = 16; o > 0; o >>= 1) {
        s  += __shfl_xor_sync(0xffffffffu, s,  o);
        sq += __shfl_xor_sync(0xffffffffu, sq, o);
    }
    __shared__ float rs[8], rq[8];
    __shared__ float s_mu, s_rstd;
    const int wid = tid >> 5, lid = tid & 31;
    if (lid == 0) { rs[wid] = s; rq[wid] = sq; }
    __syncthreads();
    if (tid == 0) {
        float ts = 0.f, tq = 0.f;
#pragma unroll
        for (int i = 0; i < 8; i++) { ts += rs[i]; tq += rq[i]; }
        float mu  = ts * (1.0f / CEMB);
        float var = tq * (1.0f / CEMB) - mu * mu;
        s_mu = mu; s_rstd = rsqrtf(var + 1e-5f);
    }
    __syncthreads();
    const float mu = s_mu, r = s_rstd;
    __half* orow = out + (size_t)row * CEMB;
    orow[tid      ] = __float2half_rn((v0 - mu) * r * g[tid      ] + b[tid      ]);
    orow[tid + 256] = __float2half_rn((v1 - mu) * r * g[tid + 256] + b[tid + 256]);
    orow[tid + 512] = __float2half_rn((v2 - mu) * r * g[tid + 512] + b[tid + 512]);
}

// ---------------------------------------------------------------------------
// HMMA GEMM: C[M,N] = A[M,K](f16) @ Bt[N,K](f16)^T + epilogue
// BM=128 BN=128 BK=64, 256 threads (8 warps, 64x32 each), 3-stage cp.async,
// XOR-swizzled 128B rows (no padding), one __syncthreads per iteration.
// EPI 1: outf = acc + bias + res
// EPI 2: outh = half(gelu(acc + bias))
// EPI 3: qkv split -> qo (scaled 1/8), ko, vo in [B*H, T, 64] fp16
// ---------------------------------------------------------------------------
#define BM 128
#define BN 128
#define BKK 64
#define TILE_BYTES (128 * 128)              // 128 rows x 128B
#define STAGE_BYTES (2 * TILE_BYTES)        // A + B
static constexpr int GEMM_SMEM = 3 * STAGE_BYTES;   // 98304 B

template <int EPI>
__global__ __launch_bounds__(256, 2) void gemm_hmma(
    int M, int N, int K,
    const __half* __restrict__ A, const __half* __restrict__ Bt,
    const float* __restrict__ bias, const float* __restrict__ res,
    float* __restrict__ outf, __half* __restrict__ outh,
    __half* __restrict__ qo, __half* __restrict__ ko, __half* __restrict__ vo)
{
    extern __shared__ __align__(16) char dynsm[];

    const int tid  = threadIdx.x;
    const int lane = tid & 31, wid = tid >> 5;
    const int wr = wid >> 2, wc = wid & 3;
    const int cRow = blockIdx.y * BM, cCol = blockIdx.x * BN;

    const uint32_t s0 = smem_u32(dynsm);
    uint32_t sA[3], sB[3];
#pragma unroll
    for (int i = 0; i < 3; i++) {
        sA[i] = s0 + i * STAGE_BYTES;
        sB[i] = sA[i] + TILE_BYTES;
    }

    // cp.async mapping: 1024 16B-chunks per tile; c = i*256+tid
    const int ldrow0 = tid >> 3;            // +32 per i (rows 0..127 over 4 iters? no:)
    // c = i*256 + tid -> row = c>>3 = i*32 + (tid>>3), chunk = tid&7
    const int ldchunk = tid & 7;
    // swizzled byte offset within tile for (row, chunk):
    //   row*128 + (chunk*16 ^ ((row&7)<<4));  row&7 == (tid>>3)&7 (i*32 keeps it)
    const uint32_t ldxor = (uint32_t)((ldchunk * 16) ^ (((tid >> 3) & 7) << 4));

    // ldmatrix addressing
    const int a_row = wr * 64 + (lane & 15);
    const uint32_t a_rowbase = (uint32_t)(a_row * 128);
    const uint32_t a_xm = (uint32_t)((a_row & 7) << 4);
    const int b_row = wc * 32 + (lane & 7) + ((lane >> 3) & 1) * 8;
    const uint32_t b_rowbase = (uint32_t)(b_row * 128);
    const uint32_t b_xm = (uint32_t)((b_row & 7) << 4);
    const uint32_t kb0 = (uint32_t)((lane >> 4) * 16);   // 0 or 16 bytes
    uint32_t colA[4], colB[4];
#pragma unroll
    for (int ks = 0; ks < 4; ks++) {
        colA[ks] = (kb0 + ks * 32) ^ a_xm;
        colB[ks] = (kb0 + ks * 32) ^ b_xm;
    }

    float acc[4][4][4];
#pragma unroll
    for (int i = 0; i < 4; i++)
#pragma unroll
        for (int j = 0; j < 4; j++)
#pragma unroll
            for (int q = 0; q < 4; q++) acc[i][j][q] = 0.f;

    const int nK = K / BKK;   // >= 3 for all our shapes

#define LOAD_TILES(kt, buf) do {                                               \
    const __half* Ag = A  + (size_t)cRow * K + (kt) * BKK;                     \
    const __half* Bg = Bt + (size_t)cCol * K + (kt) * BKK;                     \
    const uint32_t sa = sA[buf], sb = sB[buf];                                 \
    _Pragma("unroll")                                                          \
    for (int i = 0; i < 4; i++) {                                              \
        const int row = i * 32 + ldrow0;                                       \
        const uint32_t so = (uint32_t)(row * 128) + ldxor;                     \
        cp_async16(sa + so, Ag + (size_t)row * K + ldchunk * 8);               \
        cp_async16(sb + so, Bg + (size_t)row * K + ldchunk * 8);               \
    }                                                                          \
} while (0)

    LOAD_TILES(0, 0);
    CP_COMMIT();
    LOAD_TILES(1, 1);
    CP_COMMIT();

    int buf = 0, lb = 2;
    for (int kt = 0; kt < nK; ++kt) {
        if (kt + 1 < nK) { CP_WAIT(1); } else { CP_WAIT(0); }
        __syncthreads();
        if (kt + 2 < nK) {
            LOAD_TILES(kt + 2, lb);
            CP_COMMIT();
        }
        const uint32_t sa = sA[buf], sb = sB[buf];
#pragma unroll
        for (int ks = 0; ks < 4; ++ks) {
            uint32_t af[4][4];
            uint32_t bf[4][2];
#pragma unroll
            for (int mi = 0; mi < 4; mi++)
                ldsm4(af[mi], sa + a_rowbase + mi * 2048 + colA[ks]);
#pragma unroll
            for (int nj = 0; nj < 2; nj++) {
                uint32_t r[4];
                ldsm4(r, sb + b_rowbase + nj * 2048 + colB[ks]);
                bf[nj * 2][0]     = r[0]; bf[nj * 2][1]     = r[2];
                bf[nj * 2 + 1][0] = r[1]; bf[nj * 2 + 1][1] = r[3];
            }
#pragma unroll
            for (int mi = 0; mi < 4; mi++)
#pragma unroll
                for (int ni = 0; ni < 4; ni++)
                    mma16816(acc[mi][ni], af[mi], bf[ni]);
        }
        buf = (buf == 2) ? 0 : buf + 1;
        lb  = (lb  == 2) ? 0 : lb  + 1;
    }
#undef LOAD_TILES

    const int er = lane >> 2, ec = (lane & 3) * 2;
#pragma unroll
    for (int mi = 0; mi < 4; mi++) {
        const int r0 = cRow + wr * 64 + mi * 16 + er;
#pragma unroll
        for (int ni = 0; ni < 4; ni++) {
            const int col = cCol + wc * 32 + ni * 8 + ec;
            const float b0 = bias[col], b1 = bias[col + 1];
            const float* c = acc[mi][ni];
            if (EPI == 2) {
                *(__half2*)(outh + (size_t)r0 * N + col) =
                    __floats2half2_rn(gelu_f(c[0] + b0), gelu_f(c[1] + b1));
                *(__half2*)(outh + (size_t)(r0 + 8) * N + col) =
                    __floats2half2_rn(gelu_f(c[2] + b0), gelu_f(c[3] + b1));
            } else if (EPI == 3) {
                const int which = col / CEMB;
                const int rem = col - which * CEMB;
                const int hh = rem >> 6, dd = rem & 63;
                const float sc = (which == 0) ? 0.125f : 1.0f;
                __half* dst = (which == 0) ? qo : (which == 1) ? ko : vo;
#pragma unroll
                for (int half_i = 0; half_i < 2; half_i++) {
                    const int rr = r0 + half_i * 8;
                    const int bb = rr >> 11, tt = rr & 2047;
                    const size_t off = (((size_t)(bb * NHEAD + hh) * TSEQ + tt) * HDIM + dd);
                    *(__half2*)(dst + off) = __floats2half2_rn(
                        (c[half_i * 2] + b0) * sc, (c[half_i * 2 + 1] + b1) * sc);
                }
            } else {
                float2 v0 = make_float2(c[0] + b0, c[1] + b1);
                float2 v1 = make_float2(c[2] + b0, c[3] + b1);
                if (EPI == 1) {
                    float2 q0 = *(const float2*)(res + (size_t)r0 * N + col);
                    float2 q1 = *(const float2*)(res + (size_t)(r0 + 8) * N + col);
                    v0.x += q0.x; v0.y += q0.y; v1.x += q1.x; v1.y += q1.y;
                }
                *(float2*)(outf + (size_t)r0 * N + col)       = v0;
                *(float2*)(outf + (size_t)(r0 + 8) * N + col) = v1;
            }
        }
    }
}

// ---------------------------------------------------------------------------
// Flash attention (HMMA): 64 queries/CTA, 4 warps, fp16 in/out, fp32 softmax.
// Q pre-scaled by 1/8. grid = (T/64, B*H), block 128.
// ---------------------------------------------------------------------------
#define AT_ST 72   // padded halves per row

__global__ __launch_bounds__(128) void fattn_kernel(
    const __half* __restrict__ Qg, const __half* __restrict__ Kg,
    const __half* __restrict__ Vg, __half* __restrict__ y)
{
    __shared__ __align__(16) __half sQ[64 * AT_ST];
    __shared__ __align__(16) __half sK[2][64 * AT_ST];
    __shared__ __align__(16) __half sV[2][64 * AT_ST];

    const int tid = threadIdx.x, lane = tid & 31, w = tid >> 5;
    const int bh = blockIdx.y;
    const int q0 = blockIdx.x * 64;
    const size_t base = (size_t)bh * TSEQ * HDIM;
    const int nt = q0 / 64 + 1;

#define LOADKV(kt, buf) do {                                                   \
    const __half* kg = Kg + base + (size_t)(kt) * 64 * HDIM;                   \
    const __half* vg = Vg + base + (size_t)(kt) * 64 * HDIM;                   \
    _Pragma("unroll")                                                          \
    for (int i = 0; i < 4; i++) {                                              \
        const int c = tid * 4 + i;                                             \
        const int row = c >> 3, off = (c & 7) * 8;                             \
        cp_async16(smem_u32(&sK[buf][row * AT_ST + off]), kg + row * HDIM + off); \
        cp_async16(smem_u32(&sV[buf][row * AT_ST + off]), vg + row * HDIM + off); \
    }                                                                          \
} while (0)

    {
        const __half* qg = Qg + base + (size_t)q0 * HDIM;
#pragma unroll
        for (int i = 0; i < 4; i++) {
            const int c = tid * 4 + i;
            const int row = c >> 3, off = (c & 7) * 8;
            cp_async16(smem_u32(&sQ[row * AT_ST + off]), qg + row * HDIM + off);
        }
        LOADKV(0, 0);
        CP_COMMIT();
    }

    const uint32_t qbase = smem_u32(sQ) +
        (uint32_t)(((w * 16 + (lane & 15)) * AT_ST + (lane >> 4) * 8) * 2);
    const int nrow = (lane & 7) + ((lane >> 3) & 1) * 8;
    const int coff = (lane >> 4) * 8;
    const int er = lane >> 2, ec = (lane & 3) * 2;

    float m0 = -1e30f, m1 = -1e30f, l0 = 0.f, l1 = 0.f;
    float o[8][4];
#pragma unroll
    for (int i = 0; i < 8; i++)
#pragma unroll
        for (int j = 0; j < 4; j++) o[i][j] = 0.f;

    for (int kt = 0; kt < nt; ++kt) {
        const int buf = kt & 1;
        if (kt + 1 < nt) { LOADKV(kt + 1, buf ^ 1); CP_COMMIT(); CP_WAIT(1); }
        else             { CP_WAIT(0); }
        __syncthreads();

        const uint32_t kb = smem_u32(sK[buf]);
        const uint32_t vb = smem_u32(sV[buf]);

        // ---- S = Q @ K^T  (64 keys)
        float s[8][4];
#pragma unroll
        for (int i = 0; i < 8; i++)
#pragma unroll
            for (int j = 0; j < 4; j++) s[i][j] = 0.f;

#pragma unroll
        for (int ks = 0; ks < 4; ++ks) {
            uint32_t aQ[4];
            ldsm4(aQ, qbase + ks * 32);
#pragma unroll
            for (int nj = 0; nj < 4; nj++) {
                uint32_t r[4];
                ldsm4(r, kb + (uint32_t)(((nj * 16 + nrow) * AT_ST + ks * 16 + coff) * 2));
                uint32_t bA[2] = { r[0], r[2] }, bB[2] = { r[1], r[3] };
                mma16816(s[nj * 2],     aQ, bA);
                mma16816(s[nj * 2 + 1], aQ, bB);
            }
        }

        // ---- causal mask (diagonal tile only)
        if (kt == nt - 1) {
            const int r0w = w * 16 + er, r1w = r0w + 8;
#pragma unroll
            for (int n = 0; n < 8; n++) {
                const int c0 = n * 8 + ec;
                if (c0     > r0w) s[n][0] = -1e30f;
                if (c0 + 1 > r0w) s[n][1] = -1e30f;
                if (c0     > r1w) s[n][2] = -1e30f;
                if (c0 + 1 > r1w) s[n][3] = -1e30f;
            }
        }

        // ---- online softmax
        float mx0 = -1e30f, mx1 = -1e30f;
#pragma unroll
        for (int n = 0; n < 8; n++) {
            mx0 = fmaxf(mx0, fmaxf(s[n][0], s[n][1]));
            mx1 = fmaxf(mx1, fmaxf(s[n][2], s[n][3]));
        }
        mx0 = fmaxf(mx0, __shfl_xor_sync(0xffffffffu, mx0, 1));
        mx0 = fmaxf(mx0, __shfl_xor_sync(0xffffffffu, mx0, 2));
        mx1 = fmaxf(mx1, __shfl_xor_sync(0xffffffffu, mx1, 1));
        mx1 = fmaxf(mx1, __shfl_xor_sync(0xffffffffu, mx1, 2));

        const float mn0 = fmaxf(m0, mx0), mn1 = fmaxf(m1, mx1);
        const float f0 = __expf(m0 - mn0), f1 = __expf(m1 - mn1);
        float sum0 = 0.f, sum1 = 0.f;
#pragma unroll
        for (int n = 0; n < 8; n++) {
            s[n][0] = __expf(s[n][0] - mn0); sum0 += s[n][0];
            s[n][1] = __expf(s[n][1] - mn0); sum0 += s[n][1];
            s[n][2] = __expf(s[n][2] - mn1); sum1 += s[n][2];
            s[n][3] = __expf(s[n][3] - mn1); sum1 += s[n][3];
        }
        sum0 += __shfl_xor_sync(0xffffffffu, sum0, 1);
        sum0 += __shfl_xor_sync(0xffffffffu, sum0, 2);
        sum1 += __shfl_xor_sync(0xffffffffu, sum1, 1);
        sum1 += __shfl_xor_sync(0xffffffffu, sum1, 2);
        l0 = l0 * f0 + sum0;
        l1 = l1 * f1 + sum1;
        m0 = mn0; m1 = mn1;
#pragma unroll
        for (int n = 0; n < 8; n++) {
            o[n][0] *= f0; o[n][1] *= f0;
            o[n][2] *= f1; o[n][3] *= f1;
        }

        // ---- O += P @ V
#pragma unroll
        for (int ks = 0; ks < 4; ++ks) {
            uint32_t aP[4];
            aP[0] = f2h2(s[ks * 2][0],     s[ks * 2][1]);
            aP[1] = f2h2(s[ks * 2][2],     s[ks * 2][3]);
            aP[2] = f2h2(s[ks * 2 + 1][0], s[ks * 2 + 1][1]);
            aP[3] = f2h2(s[ks * 2 + 1][2], s[ks * 2 + 1][3]);
#pragma unroll
            for (int ng = 0; ng < 4; ng++) {
                uint32_t r[4];
                ldsm4t(r, vb + (uint32_t)(((ks * 16 + nrow) * AT_ST + ng * 16 + coff) * 2));
                uint32_t bA[2] = { r[0], r[1] }, bB[2] = { r[2], r[3] };
                mma16816(o[ng * 2],     aP, bA);
                mma16816(o[ng * 2 + 1], aP, bB);
            }
        }
        __syncthreads();
    }
#undef LOADKV

    const float inv0 = 1.0f / l0, inv1 = 1.0f / l1;
    const int b = bh / NHEAD, h = bh - b * NHEAD;
    const int row0 = q0 + w * 16 + er;
    __half* yp = y + ((size_t)b * TSEQ + row0) * CEMB + h * HDIM;
#pragma unroll
    for (int ng = 0; ng < 8; ng++) {
        const int col = ng * 8 + ec;
        *(__half2*)(yp + col) = __floats2half2_rn(o[ng][0] * inv0, o[ng][1] * inv0);
        *(__half2*)(yp + (size_t)8 * CEMB + col) =
            __floats2half2_rn(o[ng][2] * inv1, o[ng][3] * inv1);
    }
}

// ---------------------------------------------------------------------------
// Launch
// ---------------------------------------------------------------------------
extern "C" void kernel_launch(void* const* d_in, const int* in_sizes, int n_in,
                              void* d_out, int out_size)
{
    const float* x           = (const float*)d_in[0];
    const float* ln1_g       = (const float*)d_in[1];
    const float* ln1_b       = (const float*)d_in[2];
    const float* w_attn      = (const float*)d_in[3];
    const float* b_attn      = (const float*)d_in[4];
    const float* w_attn_proj = (const float*)d_in[5];
    const float* b_attn_proj = (const float*)d_in[6];
    const float* ln2_g       = (const float*)d_in[7];
    const float* ln2_b       = (const float*)d_in[8];
    const float* w_fc        = (const float*)d_in[9];
    const float* b_fc        = (const float*)d_in[10];
    const float* w_mlp_proj  = (const float*)d_in[11];
    const float* b_mlp_proj  = (const float*)d_in[12];
    float* out = (float*)d_out;

    __half *p_lnh, *p_q, *p_k, *p_v, *p_atth, *p_fch, *p_wTa, *p_wTp, *p_wTf, *p_wTm;
    float *p_x1;
    cudaGetSymbolAddress((void**)&p_lnh,  g_lnh);
    cudaGetSymbolAddress((void**)&p_q,    g_q);
    cudaGetSymbolAddress((void**)&p_k,    g_k);
    cudaGetSymbolAddress((void**)&p_v,    g_v);
    cudaGetSymbolAddress((void**)&p_atth, g_atth);
    cudaGetSymbolAddress((void**)&p_x1,   g_x1);
    cudaGetSymbolAddress((void**)&p_fch,  g_fch);
    cudaGetSymbolAddress((void**)&p_wTa,  g_wTa);
    cudaGetSymbolAddress((void**)&p_wTp,  g_wTp);
    cudaGetSymbolAddress((void**)&p_wTf,  g_wTf);
    cudaGetSymbolAddress((void**)&p_wTm,  g_wTm);

    cudaFuncSetAttribute(gemm_hmma<1>, cudaFuncAttributeMaxDynamicSharedMemorySize, GEMM_SMEM);
    cudaFuncSetAttribute(gemm_hmma<2>, cudaFuncAttributeMaxDynamicSharedMemorySize, GEMM_SMEM);
    cudaFuncSetAttribute(gemm_hmma<3>, cudaFuncAttributeMaxDynamicSharedMemorySize, GEMM_SMEM);

    const dim3 tb(32, 8);
    wtrans_kernel<<<dim3(2304 / 32,  768 / 32), tb>>>(w_attn,      p_wTa,  768, 2304);
    wtrans_kernel<<<dim3( 768 / 32,  768 / 32), tb>>>(w_attn_proj, p_wTp,  768,  768);
    wtrans_kernel<<<dim3(3072 / 32,  768 / 32), tb>>>(w_fc,        p_wTf,  768, 3072);
    wtrans_kernel<<<dim3( 768 / 32, 3072 / 32), tb>>>(w_mlp_proj,  p_wTm, 3072,  768);

    // 1. LN1 -> fp16
    ln_kernel<<<NTOK, 256>>>(x, ln1_g, ln1_b, p_lnh);

    // 2. QKV -> split fp16 Q (x1/8), K, V in [B*H, T, 64]
    gemm_hmma<3><<<dim3(2304 / BN, NTOK / BM), 256, GEMM_SMEM>>>(
        NTOK, 2304, CEMB, p_lnh, p_wTa, b_attn, nullptr, nullptr, nullptr,
        p_q, p_k, p_v);

    // 3. flash attention -> fp16 [token][C]
    fattn_kernel<<<dim3(TSEQ / 64, 2 * NHEAD), 128>>>(p_q, p_k, p_v, p_atth);

    // 4. x1 = x + att @ w_attn_proj + b (fp32)
    gemm_hmma<1><<<dim3(CEMB / BN, NTOK / BM), 256, GEMM_SMEM>>>(
        NTOK, CEMB, CEMB, p_atth, p_wTp, b_attn_proj, x, p_x1, nullptr,
        nullptr, nullptr, nullptr);

    // 5. LN2 -> fp16
    ln_kernel<<<NTOK, 256>>>(p_x1, ln2_g, ln2_b, p_lnh);

    // 6. fc = gelu(...) -> fp16
    gemm_hmma<2><<<dim3(3072 / BN, NTOK / BM), 256, GEMM_SMEM>>>(
        NTOK, 3072, CEMB, p_lnh, p_wTf, b_fc, nullptr, nullptr, p_fch,
        nullptr, nullptr, nullptr);

    // 7. out = x1 + fc @ w_mlp_proj + b (fp32)
    gemm_hmma<1><<<dim3(CEMB / BN, NTOK / BM), 256, GEMM_SMEM>>>(
        NTOK, CEMB, 4 * CEMB, p_fch, p_wTm, b_mlp_proj, p_x1, out, nullptr,
        nullptr, nullptr, nullptr);
}

// round 12
// speedup vs baseline: 7.3381x; 1.0399x over previous
#include <cuda_runtime.h>
#include <cuda_fp16.h>
#include <cstdint>
#include <math.h>

#define NTOK 4096          // B*T
#define CEMB 768
#define TSEQ 2048
#define NHEAD 12
#define HDIM 64

// ---------------------------------------------------------------------------
// Scratch
// ---------------------------------------------------------------------------
__device__ __half g_lnh [NTOK * CEMB];
__device__ __half g_q   [2 * NHEAD * TSEQ * HDIM];
__device__ __half g_k   [2 * NHEAD * TSEQ * HDIM];
__device__ __half g_v   [2 * NHEAD * TSEQ * HDIM];
__device__ __half g_atth[NTOK * CEMB];
__device__ float  g_x1  [NTOK * CEMB];
__device__ __half g_fch [NTOK * 4 * CEMB];
__device__ __half g_wTa [3 * CEMB * CEMB];   // [2304][768]
__device__ __half g_wTp [CEMB * CEMB];       // [768][768]
__device__ __half g_wTf [4 * CEMB * CEMB];   // [3072][768]
__device__ __half g_wTm [CEMB * 4 * CEMB];   // [768][3072]

// ---------------------------------------------------------------------------
// PTX helpers
// ---------------------------------------------------------------------------
__device__ __forceinline__ uint32_t smem_u32(const void* p) {
    uint32_t a;
    asm("{ .reg .u64 t; cvta.to.shared.u64 t, %1; cvt.u32.u64 %0, t; }"
        : "=r"(a) : "l"(p));
    return a;
}
__device__ __forceinline__ void cp_async16(uint32_t saddr, const void* g) {
    asm volatile("cp.async.cg.shared.global [%0], [%1], 16;" :: "r"(saddr), "l"(g));
}
#define CP_COMMIT() asm volatile("cp.async.commit_group;")
#define CP_WAIT(n)  asm volatile("cp.async.wait_group %0;" :: "n"(n))

__device__ __forceinline__ void ldsm4(uint32_t* r, uint32_t addr) {
    asm volatile("ldmatrix.sync.aligned.m8n8.x4.shared.b16 {%0,%1,%2,%3}, [%4];"
        : "=r"(r[0]), "=r"(r[1]), "=r"(r[2]), "=r"(r[3]) : "r"(addr));
}
__device__ __forceinline__ void ldsm4t(uint32_t* r, uint32_t addr) {
    asm volatile("ldmatrix.sync.aligned.m8n8.x4.trans.shared.b16 {%0,%1,%2,%3}, [%4];"
        : "=r"(r[0]), "=r"(r[1]), "=r"(r[2]), "=r"(r[3]) : "r"(addr));
}
__device__ __forceinline__ void mma16816(float* c, const uint32_t* a, const uint32_t* b) {
    asm volatile(
        "mma.sync.aligned.m16n8k16.row.col.f32.f16.f16.f32 "
        "{%0,%1,%2,%3}, {%4,%5,%6,%7}, {%8,%9}, {%0,%1,%2,%3};"
        : "+f"(c[0]), "+f"(c[1]), "+f"(c[2]), "+f"(c[3])
        : "r"(a[0]), "r"(a[1]), "r"(a[2]), "r"(a[3]), "r"(b[0]), "r"(b[1]));
}
__device__ __forceinline__ uint32_t f2h2(float a, float b) {
    __half2 h = __floats2half2_rn(a, b);
    return *reinterpret_cast<uint32_t*>(&h);
}

__device__ __forceinline__ float gelu_f(float x) {
    const float c = 0.7978845608028654f;
    float x3 = x * x * x;
    return 0.5f * x * (1.0f + tanhf(c * (x + 0.044715f * x3)));
}

// ---------------------------------------------------------------------------
// Merged weight transpose + fp32->fp16 for all four weights (one launch).
// wt[n][k] = half(w[k][n]); 32x32 tiles, block (32,8).
// ---------------------------------------------------------------------------
__global__ __launch_bounds__(256) void wtrans_all(
    const float* __restrict__ w0, __half* __restrict__ t0,
    const float* __restrict__ w1, __half* __restrict__ t1,
    const float* __restrict__ w2, __half* __restrict__ t2,
    const float* __restrict__ w3, __half* __restrict__ t3)
{
    const int bid = blockIdx.x;
    const float* w; __half* wt; int K, N, nx, local;
    if (bid < 1728)      { w = w0; wt = t0; K = 768;  N = 2304; nx = 72; local = bid; }
    else if (bid < 2304) { w = w1; wt = t1; K = 768;  N = 768;  nx = 24; local = bid - 1728; }
    else if (bid < 4608) { w = w2; wt = t2; K = 768;  N = 3072; nx = 96; local = bid - 2304; }
    else                 { w = w3; wt = t3; K = 3072; N = 768;  nx = 24; local = bid - 4608; }
    const int n0 = (local % nx) * 32, k0 = (local / nx) * 32;

    __shared__ float t[32][33];
    const int tx = threadIdx.x, ty = threadIdx.y;
#pragma unroll
    for (int i = 0; i < 32; i += 8)
        t[ty + i][tx] = w[(size_t)(k0 + ty + i) * N + n0 + tx];
    __syncthreads();
#pragma unroll
    for (int i = 0; i < 32; i += 8)
        wt[(size_t)(n0 + ty + i) * K + k0 + tx] = __float2half_rn(t[tx][ty + i]);
}

// ---------------------------------------------------------------------------
// LayerNorm -> fp16 out
// ---------------------------------------------------------------------------
__global__ __launch_bounds__(256) void ln_kernel(
    const float* __restrict__ x, const float* __restrict__ g,
    const float* __restrict__ b, __half* __restrict__ out)
{
    const int row = blockIdx.x;
    const int tid = threadIdx.x;
    const float* xr = x + (size_t)row * CEMB;

    float v0 = xr[tid], v1 = xr[tid + 256], v2 = xr[tid + 512];
    float s  = v0 + v1 + v2;
    float sq = v0 * v0 + v1 * v1 + v2 * v2;
#pragma unroll
    for (int o = 16; o > 0; o >>= 1) {
        s  += __shfl_xor_sync(0xffffffffu, s,  o);
        sq += __shfl_xor_sync(0xffffffffu, sq, o);
    }
    __shared__ float rs[8], rq[8];
    __shared__ float s_mu, s_rstd;
    const int wid = tid >> 5, lid = tid & 31;
    if (lid == 0) { rs[wid] = s; rq[wid] = sq; }
    __syncthreads();
    if (tid == 0) {
        float ts = 0.f, tq = 0.f;
#pragma unroll
        for (int i = 0; i < 8; i++) { ts += rs[i]; tq += rq[i]; }
        float mu  = ts * (1.0f / CEMB);
        float var = tq * (1.0f / CEMB) - mu * mu;
        s_mu = mu; s_rstd = rsqrtf(var + 1e-5f);
    }
    __syncthreads();
    const float mu = s_mu, r = s_rstd;
    __half* orow = out + (size_t)row * CEMB;
    orow[tid      ] = __float2half_rn((v0 - mu) * r * g[tid      ] + b[tid      ]);
    orow[tid + 256] = __float2half_rn((v1 - mu) * r * g[tid + 256] + b[tid + 256]);
    orow[tid + 512] = __float2half_rn((v2 - mu) * r * g[tid + 512] + b[tid + 512]);
}

// ---------------------------------------------------------------------------
// HMMA GEMM: C[M,N] = A[M,K](f16) @ Bt[N,K](f16)^T + epilogue
// BM=128 BN=128 BK=64, 256 threads, 3-stage cp.async, XOR swizzle.
// EPI 1: outf = acc + bias + res
// EPI 2: outh = half(gelu(acc + bias))
// EPI 3: qkv split -> qo (scaled 1/8), ko, vo in [B*H, T, 64] fp16
// ---------------------------------------------------------------------------
#define BM 128
#define BN 128
#define BKK 64
#define TILE_BYTES (128 * 128)
#define STAGE_BYTES (2 * TILE_BYTES)
static constexpr int GEMM_SMEM = 3 * STAGE_BYTES;   // 98304 B

template <int EPI>
__global__ __launch_bounds__(256, 2) void gemm_hmma(
    int M, int N, int K,
    const __half* __restrict__ A, const __half* __restrict__ Bt,
    const float* __restrict__ bias, const float* __restrict__ res,
    float* __restrict__ outf, __half* __restrict__ outh,
    __half* __restrict__ qo, __half* __restrict__ ko, __half* __restrict__ vo)
{
    extern __shared__ __align__(16) char dynsm[];

    const int tid  = threadIdx.x;
    const int lane = tid & 31, wid = tid >> 5;
    const int wr = wid >> 2, wc = wid & 3;
    const int cRow = blockIdx.y * BM, cCol = blockIdx.x * BN;

    const uint32_t s0 = smem_u32(dynsm);
    uint32_t sA[3], sB[3];
#pragma unroll
    for (int i = 0; i < 3; i++) {
        sA[i] = s0 + i * STAGE_BYTES;
        sB[i] = sA[i] + TILE_BYTES;
    }

    const int ldrow0 = tid >> 3;
    const int ldchunk = tid & 7;
    const uint32_t ldxor = (uint32_t)((ldchunk * 16) ^ (((tid >> 3) & 7) << 4));

    const int a_row = wr * 64 + (lane & 15);
    const uint32_t a_rowbase = (uint32_t)(a_row * 128);
    const uint32_t a_xm = (uint32_t)((a_row & 7) << 4);
    const int b_row = wc * 32 + (lane & 7) + ((lane >> 3) & 1) * 8;
    const uint32_t b_rowbase = (uint32_t)(b_row * 128);
    const uint32_t b_xm = (uint32_t)((b_row & 7) << 4);
    const uint32_t kb0 = (uint32_t)((lane >> 4) * 16);
    uint32_t colA[4], colB[4];
#pragma unroll
    for (int ks = 0; ks < 4; ks++) {
        colA[ks] = (kb0 + ks * 32) ^ a_xm;
        colB[ks] = (kb0 + ks * 32) ^ b_xm;
    }

    float acc[4][4][4];
#pragma unroll
    for (int i = 0; i < 4; i++)
#pragma unroll
        for (int j = 0; j < 4; j++)
#pragma unroll
            for (int q = 0; q < 4; q++) acc[i][j][q] = 0.f;

    const int nK = K / BKK;

#define LOAD_TILES(kt, buf) do {                                               \
    const __half* Ag = A  + (size_t)cRow * K + (kt) * BKK;                     \
    const __half* Bg = Bt + (size_t)cCol * K + (kt) * BKK;                     \
    const uint32_t sa = sA[buf], sb = sB[buf];                                 \
    _Pragma("unroll")                                                          \
    for (int i = 0; i < 4; i++) {                                              \
        const int row = i * 32 + ldrow0;                                       \
        const uint32_t so = (uint32_t)(row * 128) + ldxor;                     \
        cp_async16(sa + so, Ag + (size_t)row * K + ldchunk * 8);               \
        cp_async16(sb + so, Bg + (size_t)row * K + ldchunk * 8);               \
    }                                                                          \
} while (0)

    LOAD_TILES(0, 0);
    CP_COMMIT();
    LOAD_TILES(1, 1);
    CP_COMMIT();

    int buf = 0, lb = 2;
    for (int kt = 0; kt < nK; ++kt) {
        if (kt + 1 < nK) { CP_WAIT(1); } else { CP_WAIT(0); }
        __syncthreads();
        if (kt + 2 < nK) {
            LOAD_TILES(kt + 2, lb);
            CP_COMMIT();
        }
        const uint32_t sa = sA[buf], sb = sB[buf];
#pragma unroll
        for (int ks = 0; ks < 4; ++ks) {
            uint32_t af[4][4];
            uint32_t bf[4][2];
#pragma unroll
            for (int mi = 0; mi < 4; mi++)
                ldsm4(af[mi], sa + a_rowbase + mi * 2048 + colA[ks]);
#pragma unroll
            for (int nj = 0; nj < 2; nj++) {
                uint32_t r[4];
                ldsm4(r, sb + b_rowbase + nj * 2048 + colB[ks]);
                bf[nj * 2][0]     = r[0]; bf[nj * 2][1]     = r[2];
                bf[nj * 2 + 1][0] = r[1]; bf[nj * 2 + 1][1] = r[3];
            }
#pragma unroll
            for (int mi = 0; mi < 4; mi++)
#pragma unroll
                for (int ni = 0; ni < 4; ni++)
                    mma16816(acc[mi][ni], af[mi], bf[ni]);
        }
        buf = (buf == 2) ? 0 : buf + 1;
        lb  = (lb  == 2) ? 0 : lb  + 1;
    }
#undef LOAD_TILES

    const int er = lane >> 2, ec = (lane & 3) * 2;
#pragma unroll
    for (int mi = 0; mi < 4; mi++) {
        const int r0 = cRow + wr * 64 + mi * 16 + er;
#pragma unroll
        for (int ni = 0; ni < 4; ni++) {
            const int col = cCol + wc * 32 + ni * 8 + ec;
            const float b0 = bias[col], b1 = bias[col + 1];
            const float* c = acc[mi][ni];
            if (EPI == 2) {
                *(__half2*)(outh + (size_t)r0 * N + col) =
                    __floats2half2_rn(gelu_f(c[0] + b0), gelu_f(c[1] + b1));
                *(__half2*)(outh + (size_t)(r0 + 8) * N + col) =
                    __floats2half2_rn(gelu_f(c[2] + b0), gelu_f(c[3] + b1));
            } else if (EPI == 3) {
                const int which = col / CEMB;
                const int rem = col - which * CEMB;
                const int hh = rem >> 6, dd = rem & 63;
                const float sc = (which == 0) ? 0.125f : 1.0f;
                __half* dst = (which == 0) ? qo : (which == 1) ? ko : vo;
#pragma unroll
                for (int half_i = 0; half_i < 2; half_i++) {
                    const int rr = r0 + half_i * 8;
                    const int bb = rr >> 11, tt = rr & 2047;
                    const size_t off = (((size_t)(bb * NHEAD + hh) * TSEQ + tt) * HDIM + dd);
                    *(__half2*)(dst + off) = __floats2half2_rn(
                        (c[half_i * 2] + b0) * sc, (c[half_i * 2 + 1] + b1) * sc);
                }
            } else {
                float2 v0 = make_float2(c[0] + b0, c[1] + b1);
                float2 v1 = make_float2(c[2] + b0, c[3] + b1);
                if (EPI == 1) {
                    float2 q0 = *(const float2*)(res + (size_t)r0 * N + col);
                    float2 q1 = *(const float2*)(res + (size_t)(r0 + 8) * N + col);
                    v0.x += q0.x; v0.y += q0.y; v1.x += q1.x; v1.y += q1.y;
                }
                *(float2*)(outf + (size_t)r0 * N + col)       = v0;
                *(float2*)(outf + (size_t)(r0 + 8) * N + col) = v1;
            }
        }
    }
}

// ---------------------------------------------------------------------------
// Flash attention (HMMA): 128 queries/CTA, 8 warps, fp16 in/out, fp32 softmax.
// Q pre-scaled by 1/8. grid = (T/128, B*H), block 256, dynamic smem.
// ---------------------------------------------------------------------------
#define AT_ST 72                               // padded halves per row
#define ATQ_HALVES (128 * AT_ST)               // 9216
#define ATKV_HALVES (64 * AT_ST)               // 4608
static constexpr int ATTN_SMEM = (ATQ_HALVES + 4 * ATKV_HALVES) * 2;  // 55296 B

__global__ __launch_bounds__(256) void fattn_kernel(
    const __half* __restrict__ Qg, const __half* __restrict__ Kg,
    const __half* __restrict__ Vg, __half* __restrict__ y)
{
    extern __shared__ __align__(16) __half atsm[];
    __half* sQ = atsm;                              // 128 rows
    __half* sK = atsm + ATQ_HALVES;                 // [2][64 rows]
    __half* sV = atsm + ATQ_HALVES + 2 * ATKV_HALVES;

    const int tid = threadIdx.x, lane = tid & 31, w = tid >> 5;
    const int bh = blockIdx.y;
    const int q0 = blockIdx.x * 128;
    const size_t base = (size_t)bh * TSEQ * HDIM;
    const int nt = q0 / 64 + 2;

#define LOADKV(kt, bufi) do {                                                  \
    const __half* kg = Kg + base + (size_t)(kt) * 64 * HDIM;                   \
    const __half* vg = Vg + base + (size_t)(kt) * 64 * HDIM;                   \
    __half* kd = sK + (bufi) * ATKV_HALVES;                                    \
    __half* vd = sV + (bufi) * ATKV_HALVES;                                    \
    _Pragma("unroll")                                                          \
    for (int i = 0; i < 2; i++) {                                              \
        const int c = tid * 2 + i;                                             \
        const int row = c >> 3, off = (c & 7) * 8;                             \
        cp_async16(smem_u32(kd + row * AT_ST + off), kg + row * HDIM + off);   \
        cp_async16(smem_u32(vd + row * AT_ST + off), vg + row * HDIM + off);   \
    }                                                                          \
} while (0)

    {
        const __half* qg = Qg + base + (size_t)q0 * HDIM;
#pragma unroll
        for (int i = 0; i < 4; i++) {
            const int c = tid * 4 + i;
            const int row = c >> 3, off = (c & 7) * 8;
            cp_async16(smem_u32(sQ + row * AT_ST + off), qg + row * HDIM + off);
        }
        LOADKV(0, 0);
        CP_COMMIT();
    }

    const uint32_t qbase = smem_u32(sQ) +
        (uint32_t)(((w * 16 + (lane & 15)) * AT_ST + (lane >> 4) * 8) * 2);
    const int nrow = (lane & 7) + ((lane >> 3) & 1) * 8;
    const int coff = (lane >> 4) * 8;
    const int er = lane >> 2, ec = (lane & 3) * 2;
    const int qwarp = q0 + w * 16;                  // warp's first q row

    float m0 = -1e30f, m1 = -1e30f, l0 = 0.f, l1 = 0.f;
    float o[8][4];
#pragma unroll
    for (int i = 0; i < 8; i++)
#pragma unroll
        for (int j = 0; j < 4; j++) o[i][j] = 0.f;

    for (int kt = 0; kt < nt; ++kt) {
        const int bufi = kt & 1;
        if (kt + 1 < nt) { LOADKV(kt + 1, bufi ^ 1); CP_COMMIT(); CP_WAIT(1); }
        else             { CP_WAIT(0); }
        __syncthreads();

        const bool active = (kt * 64) <= (qwarp + 15);
        if (active) {
            const uint32_t kb = smem_u32(sK + bufi * ATKV_HALVES);
            const uint32_t vb = smem_u32(sV + bufi * ATKV_HALVES);

            // ---- S = Q @ K^T (64 keys)
            float s[8][4];
#pragma unroll
            for (int i = 0; i < 8; i++)
#pragma unroll
                for (int j = 0; j < 4; j++) s[i][j] = 0.f;

#pragma unroll
            for (int ks = 0; ks < 4; ++ks) {
                uint32_t aQ[4];
                ldsm4(aQ, qbase + ks * 32);
#pragma unroll
                for (int nj = 0; nj < 4; nj++) {
                    uint32_t r[4];
                    ldsm4(r, kb + (uint32_t)(((nj * 16 + nrow) * AT_ST + ks * 16 + coff) * 2));
                    uint32_t bA[2] = { r[0], r[2] }, bB[2] = { r[1], r[3] };
                    mma16816(s[nj * 2],     aQ, bA);
                    mma16816(s[nj * 2 + 1], aQ, bB);
                }
            }

            // ---- causal mask (global indices; only near-diagonal tiles)
            if (kt * 64 + 63 > qwarp) {
                const int r0w = qwarp + er, r1w = r0w + 8;
                const int j0 = kt * 64;
#pragma unroll
                for (int n = 0; n < 8; n++) {
                    const int c0 = j0 + n * 8 + ec;
                    if (c0     > r0w) s[n][0] = -1e30f;
                    if (c0 + 1 > r0w) s[n][1] = -1e30f;
                    if (c0     > r1w) s[n][2] = -1e30f;
                    if (c0 + 1 > r1w) s[n][3] = -1e30f;
                }
            }

            // ---- online softmax
            float mx0 = -1e30f, mx1 = -1e30f;
#pragma unroll
            for (int n = 0; n < 8; n++) {
                mx0 = fmaxf(mx0, fmaxf(s[n][0], s[n][1]));
                mx1 = fmaxf(mx1, fmaxf(s[n][2], s[n][3]));
            }
            mx0 = fmaxf(mx0, __shfl_xor_sync(0xffffffffu, mx0, 1));
            mx0 = fmaxf(mx0, __shfl_xor_sync(0xffffffffu, mx0, 2));
            mx1 = fmaxf(mx1, __shfl_xor_sync(0xffffffffu, mx1, 1));
            mx1 = fmaxf(mx1, __shfl_xor_sync(0xffffffffu, mx1, 2));

            const float mn0 = fmaxf(m0, mx0), mn1 = fmaxf(m1, mx1);
            const float f0 = __expf(m0 - mn0), f1 = __expf(m1 - mn1);
            float sum0 = 0.f, sum1 = 0.f;
#pragma unroll
            for (int n = 0; n < 8; n++) {
                s[n][0] = __expf(s[n][0] - mn0); sum0 += s[n][0];
                s[n][1] = __expf(s[n][1] - mn0); sum0 += s[n][1];
                s[n][2] = __expf(s[n][2] - mn1); sum1 += s[n][2];
                s[n][3] = __expf(s[n][3] - mn1); sum1 += s[n][3];
            }
            sum0 += __shfl_xor_sync(0xffffffffu, sum0, 1);
            sum0 += __shfl_xor_sync(0xffffffffu, sum0, 2);
            sum1 += __shfl_xor_sync(0xffffffffu, sum1, 1);
            sum1 += __shfl_xor_sync(0xffffffffu, sum1, 2);
            l0 = l0 * f0 + sum0;
            l1 = l1 * f1 + sum1;
            m0 = mn0; m1 = mn1;
#pragma unroll
            for (int n = 0; n < 8; n++) {
                o[n][0] *= f0; o[n][1] *= f0;
                o[n][2] *= f1; o[n][3] *= f1;
            }

            // ---- O += P @ V
#pragma unroll
            for (int ks = 0; ks < 4; ++ks) {
                uint32_t aP[4];
                aP[0] = f2h2(s[ks * 2][0],     s[ks * 2][1]);
                aP[1] = f2h2(s[ks * 2][2],     s[ks * 2][3]);
                aP[2] = f2h2(s[ks * 2 + 1][0], s[ks * 2 + 1][1]);
                aP[3] = f2h2(s[ks * 2 + 1][2], s[ks * 2 + 1][3]);
#pragma unroll
                for (int ng = 0; ng < 4; ng++) {
                    uint32_t r[4];
                    ldsm4t(r, vb + (uint32_t)(((ks * 16 + nrow) * AT_ST + ng * 16 + coff) * 2));
                    uint32_t bA[2] = { r[0], r[1] }, bB[2] = { r[2], r[3] };
                    mma16816(o[ng * 2],     aP, bA);
                    mma16816(o[ng * 2 + 1], aP, bB);
                }
            }
        }
        __syncthreads();
    }
#undef LOADKV

    const float inv0 = 1.0f / l0, inv1 = 1.0f / l1;
    const int b = bh / NHEAD, h = bh - b * NHEAD;
    const int row0 = q0 + w * 16 + er;
    __half* yp = y + ((size_t)b * TSEQ + row0) * CEMB + h * HDIM;
#pragma unroll
    for (int ng = 0; ng < 8; ng++) {
        const int col = ng * 8 + ec;
        *(__half2*)(yp + col) = __floats2half2_rn(o[ng][0] * inv0, o[ng][1] * inv0);
        *(__half2*)(yp + (size_t)8 * CEMB + col) =
            __floats2half2_rn(o[ng][2] * inv1, o[ng][3] * inv1);
    }
}

// ---------------------------------------------------------------------------
// Launch
// ---------------------------------------------------------------------------
extern "C" void kernel_launch(void* const* d_in, const int* in_sizes, int n_in,
                              void* d_out, int out_size)
{
    const float* x           = (const float*)d_in[0];
    const float* ln1_g       = (const float*)d_in[1];
    const float* ln1_b       = (const float*)d_in[2];
    const float* w_attn      = (const float*)d_in[3];
    const float* b_attn      = (const float*)d_in[4];
    const float* w_attn_proj = (const float*)d_in[5];
    const float* b_attn_proj = (const float*)d_in[6];
    const float* ln2_g       = (const float*)d_in[7];
    const float* ln2_b       = (const float*)d_in[8];
    const float* w_fc        = (const float*)d_in[9];
    const float* b_fc        = (const float*)d_in[10];
    const float* w_mlp_proj  = (const float*)d_in[11];
    const float* b_mlp_proj  = (const float*)d_in[12];
    float* out = (float*)d_out;

    __half *p_lnh, *p_q, *p_k, *p_v, *p_atth, *p_fch, *p_wTa, *p_wTp, *p_wTf, *p_wTm;
    float *p_x1;
    cudaGetSymbolAddress((void**)&p_lnh,  g_lnh);
    cudaGetSymbolAddress((void**)&p_q,    g_q);
    cudaGetSymbolAddress((void**)&p_k,    g_k);
    cudaGetSymbolAddress((void**)&p_v,    g_v);
    cudaGetSymbolAddress((void**)&p_atth, g_atth);
    cudaGetSymbolAddress((void**)&p_x1,   g_x1);
    cudaGetSymbolAddress((void**)&p_fch,  g_fch);
    cudaGetSymbolAddress((void**)&p_wTa,  g_wTa);
    cudaGetSymbolAddress((void**)&p_wTp,  g_wTp);
    cudaGetSymbolAddress((void**)&p_wTf,  g_wTf);
    cudaGetSymbolAddress((void**)&p_wTm,  g_wTm);

    cudaFuncSetAttribute(gemm_hmma<1>, cudaFuncAttributeMaxDynamicSharedMemorySize, GEMM_SMEM);
    cudaFuncSetAttribute(gemm_hmma<2>, cudaFuncAttributeMaxDynamicSharedMemorySize, GEMM_SMEM);
    cudaFuncSetAttribute(gemm_hmma<3>, cudaFuncAttributeMaxDynamicSharedMemorySize, GEMM_SMEM);
    cudaFuncSetAttribute(fattn_kernel, cudaFuncAttributeMaxDynamicSharedMemorySize, ATTN_SMEM);

    // weight transposes (merged, one launch)
    wtrans_all<<<6912, dim3(32, 8)>>>(w_attn, p_wTa, w_attn_proj, p_wTp,
                                      w_fc, p_wTf, w_mlp_proj, p_wTm);

    // 1. LN1 -> fp16
    ln_kernel<<<NTOK, 256>>>(x, ln1_g, ln1_b, p_lnh);

    // 2. QKV -> split fp16 Q (x1/8), K, V in [B*H, T, 64]
    gemm_hmma<3><<<dim3(2304 / BN, NTOK / BM), 256, GEMM_SMEM>>>(
        NTOK, 2304, CEMB, p_lnh, p_wTa, b_attn, nullptr, nullptr, nullptr,
        p_q, p_k, p_v);

    // 3. flash attention -> fp16 [token][C]
    fattn_kernel<<<dim3(TSEQ / 128, 2 * NHEAD), 256, ATTN_SMEM>>>(p_q, p_k, p_v, p_atth);

    // 4. x1 = x + att @ w_attn_proj + b (fp32)
    gemm_hmma<1><<<dim3(CEMB / BN, NTOK / BM), 256, GEMM_SMEM>>>(
        NTOK, CEMB, CEMB, p_atth, p_wTp, b_attn_proj, x, p_x1, nullptr,
        nullptr, nullptr, nullptr);

    // 5. LN2 -> fp16
    ln_kernel<<<NTOK, 256>>>(p_x1, ln2_g, ln2_b, p_lnh);

    // 6. fc = gelu(...) -> fp16
    gemm_hmma<2><<<dim3(3072 / BN, NTOK / BM), 256, GEMM_SMEM>>>(
        NTOK, 3072, CEMB, p_lnh, p_wTf, b_fc, nullptr, nullptr, p_fch,
        nullptr, nullptr, nullptr);

    // 7. out = x1 + fc @ w_mlp_proj + b (fp32)
    gemm_hmma<1><<<dim3(CEMB / BN, NTOK / BM), 256, GEMM_SMEM>>>(
        NTOK, CEMB, 4 * CEMB, p_fch, p_wTm, b_mlp_proj, p_x1, out, nullptr,
        nullptr, nullptr, nullptr);
}

// round 13
// speedup vs baseline: 7.4028x; 1.0088x over previous
#include <cuda_runtime.h>
#include <cuda_fp16.h>
#include <cstdint>
#include <math.h>

#define NTOK 4096          // B*T
#define CEMB 768
#define TSEQ 2048
#define NHEAD 12
#define HDIM 64

// ---------------------------------------------------------------------------
// Scratch
// ---------------------------------------------------------------------------
__device__ __half g_lnh [NTOK * CEMB];
__device__ __half g_q   [2 * NHEAD * TSEQ * HDIM];
__device__ __half g_k   [2 * NHEAD * TSEQ * HDIM];
__device__ __half g_v   [2 * NHEAD * TSEQ * HDIM];
__device__ __half g_atth[NTOK * CEMB];
__device__ float  g_x1  [NTOK * CEMB];
__device__ __half g_fch [NTOK * 4 * CEMB];
__device__ __half g_wTa [3 * CEMB * CEMB];   // [2304][768]
__device__ __half g_wTp [CEMB * CEMB];       // [768][768]
__device__ __half g_wTf [4 * CEMB * CEMB];   // [3072][768]
__device__ __half g_wTm [CEMB * 4 * CEMB];   // [768][3072]

// ---------------------------------------------------------------------------
// PTX helpers
// ---------------------------------------------------------------------------
__device__ __forceinline__ uint32_t smem_u32(const void* p) {
    uint32_t a;
    asm("{ .reg .u64 t; cvta.to.shared.u64 t, %1; cvt.u32.u64 %0, t; }"
        : "=r"(a) : "l"(p));
    return a;
}
__device__ __forceinline__ void cp_async16(uint32_t saddr, const void* g) {
    asm volatile("cp.async.cg.shared.global [%0], [%1], 16;" :: "r"(saddr), "l"(g));
}
#define CP_COMMIT() asm volatile("cp.async.commit_group;")
#define CP_WAIT(n)  asm volatile("cp.async.wait_group %0;" :: "n"(n))

__device__ __forceinline__ void ldsm4(uint32_t* r, uint32_t addr) {
    asm volatile("ldmatrix.sync.aligned.m8n8.x4.shared.b16 {%0,%1,%2,%3}, [%4];"
        : "=r"(r[0]), "=r"(r[1]), "=r"(r[2]), "=r"(r[3]) : "r"(addr));
}
__device__ __forceinline__ void ldsm4t(uint32_t* r, uint32_t addr) {
    asm volatile("ldmatrix.sync.aligned.m8n8.x4.trans.shared.b16 {%0,%1,%2,%3}, [%4];"
        : "=r"(r[0]), "=r"(r[1]), "=r"(r[2]), "=r"(r[3]) : "r"(addr));
}
__device__ __forceinline__ void mma16816(float* c, const uint32_t* a, const uint32_t* b) {
    asm volatile(
        "mma.sync.aligned.m16n8k16.row.col.f32.f16.f16.f32 "
        "{%0,%1,%2,%3}, {%4,%5,%6,%7}, {%8,%9}, {%0,%1,%2,%3};"
        : "+f"(c[0]), "+f"(c[1]), "+f"(c[2]), "+f"(c[3])
        : "r"(a[0]), "r"(a[1]), "r"(a[2]), "r"(a[3]), "r"(b[0]), "r"(b[1]));
}
__device__ __forceinline__ uint32_t f2h2(float a, float b) {
    __half2 h = __floats2half2_rn(a, b);
    return *reinterpret_cast<uint32_t*>(&h);
}

__device__ __forceinline__ float gelu_f(float x) {
    const float c = 0.7978845608028654f;
    float x3 = x * x * x;
    return 0.5f * x * (1.0f + tanhf(c * (x + 0.044715f * x3)));
}

// ---------------------------------------------------------------------------
// Merged weight transpose + fp32->fp16 for all four weights (one launch).
// ---------------------------------------------------------------------------
__global__ __launch_bounds__(256) void wtrans_all(
    const float* __restrict__ w0, __half* __restrict__ t0,
    const float* __restrict__ w1, __half* __restrict__ t1,
    const float* __restrict__ w2, __half* __restrict__ t2,
    const float* __restrict__ w3, __half* __restrict__ t3)
{
    const int bid = blockIdx.x;
    const float* w; __half* wt; int K, N, nx, local;
    if (bid < 1728)      { w = w0; wt = t0; K = 768;  N = 2304; nx = 72; local = bid; }
    else if (bid < 2304) { w = w1; wt = t1; K = 768;  N = 768;  nx = 24; local = bid - 1728; }
    else if (bid < 4608) { w = w2; wt = t2; K = 768;  N = 3072; nx = 96; local = bid - 2304; }
    else                 { w = w3; wt = t3; K = 3072; N = 768;  nx = 24; local = bid - 4608; }
    const int n0 = (local % nx) * 32, k0 = (local / nx) * 32;

    __shared__ float t[32][33];
    const int tx = threadIdx.x, ty = threadIdx.y;
#pragma unroll
    for (int i = 0; i < 32; i += 8)
        t[ty + i][tx] = w[(size_t)(k0 + ty + i) * N + n0 + tx];
    __syncthreads();
#pragma unroll
    for (int i = 0; i < 32; i += 8)
        wt[(size_t)(n0 + ty + i) * K + k0 + tx] = __float2half_rn(t[tx][ty + i]);
}

// ---------------------------------------------------------------------------
// LayerNorm -> fp16 out
// ---------------------------------------------------------------------------
__global__ __launch_bounds__(256) void ln_kernel(
    const float* __restrict__ x, const float* __restrict__ g,
    const float* __restrict__ b, __half* __restrict__ out)
{
    const int row = blockIdx.x;
    const int tid = threadIdx.x;
    const float* xr = x + (size_t)row * CEMB;

    float v0 = xr[tid], v1 = xr[tid + 256], v2 = xr[tid + 512];
    float s  = v0 + v1 + v2;
    float sq = v0 * v0 + v1 * v1 + v2 * v2;
#pragma unroll
    for (int o = 16; o > 0; o >>= 1) {
        s  += __shfl_xor_sync(0xffffffffu, s,  o);
        sq += __shfl_xor_sync(0xffffffffu, sq, o);
    }
    __shared__ float rs[8], rq[8];
    __shared__ float s_mu, s_rstd;
    const int wid = tid >> 5, lid = tid & 31;
    if (lid == 0) { rs[wid] = s; rq[wid] = sq; }
    __syncthreads();
    if (tid == 0) {
        float ts = 0.f, tq = 0.f;
#pragma unroll
        for (int i = 0; i < 8; i++) { ts += rs[i]; tq += rq[i]; }
        float mu  = ts * (1.0f / CEMB);
        float var = tq * (1.0f / CEMB) - mu * mu;
        s_mu = mu; s_rstd = rsqrtf(var + 1e-5f);
    }
    __syncthreads();
    const float mu = s_mu, r = s_rstd;
    __half* orow = out + (size_t)row * CEMB;
    orow[tid      ] = __float2half_rn((v0 - mu) * r * g[tid      ] + b[tid      ]);
    orow[tid + 256] = __float2half_rn((v1 - mu) * r * g[tid + 256] + b[tid + 256]);
    orow[tid + 512] = __float2half_rn((v2 - mu) * r * g[tid + 512] + b[tid + 512]);
}

// ---------------------------------------------------------------------------
// HMMA GEMM: C[M,N] = A[M,K](f16) @ Bt[N,K](f16)^T + epilogue
// BM=128 BN=128 BK=64, 256 threads, 3-stage cp.async, XOR swizzle.
// ---------------------------------------------------------------------------
#define BM 128
#define BN 128
#define BKK 64
#define TILE_BYTES (128 * 128)
#define STAGE_BYTES (2 * TILE_BYTES)
static constexpr int GEMM_SMEM = 3 * STAGE_BYTES;   // 98304 B

template <int EPI>
__global__ __launch_bounds__(256, 2) void gemm_hmma(
    int M, int N, int K,
    const __half* __restrict__ A, const __half* __restrict__ Bt,
    const float* __restrict__ bias, const float* __restrict__ res,
    float* __restrict__ outf, __half* __restrict__ outh,
    __half* __restrict__ qo, __half* __restrict__ ko, __half* __restrict__ vo)
{
    extern __shared__ __align__(16) char dynsm[];

    const int tid  = threadIdx.x;
    const int lane = tid & 31, wid = tid >> 5;
    const int wr = wid >> 2, wc = wid & 3;
    const int cRow = blockIdx.y * BM, cCol = blockIdx.x * BN;

    const uint32_t s0 = smem_u32(dynsm);
    uint32_t sA[3], sB[3];
#pragma unroll
    for (int i = 0; i < 3; i++) {
        sA[i] = s0 + i * STAGE_BYTES;
        sB[i] = sA[i] + TILE_BYTES;
    }

    const int ldrow0 = tid >> 3;
    const int ldchunk = tid & 7;
    const uint32_t ldxor = (uint32_t)((ldchunk * 16) ^ (((tid >> 3) & 7) << 4));

    const int a_row = wr * 64 + (lane & 15);
    const uint32_t a_rowbase = (uint32_t)(a_row * 128);
    const uint32_t a_xm = (uint32_t)((a_row & 7) << 4);
    const int b_row = wc * 32 + (lane & 7) + ((lane >> 3) & 1) * 8;
    const uint32_t b_rowbase = (uint32_t)(b_row * 128);
    const uint32_t b_xm = (uint32_t)((b_row & 7) << 4);
    const uint32_t kb0 = (uint32_t)((lane >> 4) * 16);
    uint32_t colA[4], colB[4];
#pragma unroll
    for (int ks = 0; ks < 4; ks++) {
        colA[ks] = (kb0 + ks * 32) ^ a_xm;
        colB[ks] = (kb0 + ks * 32) ^ b_xm;
    }

    float acc[4][4][4];
#pragma unroll
    for (int i = 0; i < 4; i++)
#pragma unroll
        for (int j = 0; j < 4; j++)
#pragma unroll
            for (int q = 0; q < 4; q++) acc[i][j][q] = 0.f;

    const int nK = K / BKK;

#define LOAD_TILES(kt, buf) do {                                               \
    const __half* Ag = A  + (size_t)cRow * K + (kt) * BKK;                     \
    const __half* Bg = Bt + (size_t)cCol * K + (kt) * BKK;                     \
    const uint32_t sa = sA[buf], sb = sB[buf];                                 \
    _Pragma("unroll")                                                          \
    for (int i = 0; i < 4; i++) {                                              \
        const int row = i * 32 + ldrow0;                                       \
        const uint32_t so = (uint32_t)(row * 128) + ldxor;                     \
        cp_async16(sa + so, Ag + (size_t)row * K + ldchunk * 8);               \
        cp_async16(sb + so, Bg + (size_t)row * K + ldchunk * 8);               \
    }                                                                          \
} while (0)

    LOAD_TILES(0, 0);
    CP_COMMIT();
    LOAD_TILES(1, 1);
    CP_COMMIT();

    int buf = 0, lb = 2;
    for (int kt = 0; kt < nK; ++kt) {
        if (kt + 1 < nK) { CP_WAIT(1); } else { CP_WAIT(0); }
        __syncthreads();
        if (kt + 2 < nK) {
            LOAD_TILES(kt + 2, lb);
            CP_COMMIT();
        }
        const uint32_t sa = sA[buf], sb = sB[buf];
#pragma unroll
        for (int ks = 0; ks < 4; ++ks) {
            uint32_t af[4][4];
            uint32_t bf[4][2];
#pragma unroll
            for (int mi = 0; mi < 4; mi++)
                ldsm4(af[mi], sa + a_rowbase + mi * 2048 + colA[ks]);
#pragma unroll
            for (int nj = 0; nj < 2; nj++) {
                uint32_t r[4];
                ldsm4(r, sb + b_rowbase + nj * 2048 + colB[ks]);
                bf[nj * 2][0]     = r[0]; bf[nj * 2][1]     = r[2];
                bf[nj * 2 + 1][0] = r[1]; bf[nj * 2 + 1][1] = r[3];
            }
#pragma unroll
            for (int mi = 0; mi < 4; mi++)
#pragma unroll
                for (int ni = 0; ni < 4; ni++)
                    mma16816(acc[mi][ni], af[mi], bf[ni]);
        }
        buf = (buf == 2) ? 0 : buf + 1;
        lb  = (lb  == 2) ? 0 : lb  + 1;
    }
#undef LOAD_TILES

    const int er = lane >> 2, ec = (lane & 3) * 2;
#pragma unroll
    for (int mi = 0; mi < 4; mi++) {
        const int r0 = cRow + wr * 64 + mi * 16 + er;
#pragma unroll
        for (int ni = 0; ni < 4; ni++) {
            const int col = cCol + wc * 32 + ni * 8 + ec;
            const float b0 = bias[col], b1 = bias[col + 1];
            const float* c = acc[mi][ni];
            if (EPI == 2) {
                *(__half2*)(outh + (size_t)r0 * N + col) =
                    __floats2half2_rn(gelu_f(c[0] + b0), gelu_f(c[1] + b1));
                *(__half2*)(outh + (size_t)(r0 + 8) * N + col) =
                    __floats2half2_rn(gelu_f(c[2] + b0), gelu_f(c[3] + b1));
            } else if (EPI == 3) {
                const int which = col / CEMB;
                const int rem = col - which * CEMB;
                const int hh = rem >> 6, dd = rem & 63;
                const float sc = (which == 0) ? 0.125f : 1.0f;
                __half* dst = (which == 0) ? qo : (which == 1) ? ko : vo;
#pragma unroll
                for (int half_i = 0; half_i < 2; half_i++) {
                    const int rr = r0 + half_i * 8;
                    const int bb = rr >> 11, tt = rr & 2047;
                    const size_t off = (((size_t)(bb * NHEAD + hh) * TSEQ + tt) * HDIM + dd);
                    *(__half2*)(dst + off) = __floats2half2_rn(
                        (c[half_i * 2] + b0) * sc, (c[half_i * 2 + 1] + b1) * sc);
                }
            } else {
                float2 v0 = make_float2(c[0] + b0, c[1] + b1);
                float2 v1 = make_float2(c[2] + b0, c[3] + b1);
                if (EPI == 1) {
                    float2 q0 = *(const float2*)(res + (size_t)r0 * N + col);
                    float2 q1 = *(const float2*)(res + (size_t)(r0 + 8) * N + col);
                    v0.x += q0.x; v0.y += q0.y; v1.x += q1.x; v1.y += q1.y;
                }
                *(float2*)(outf + (size_t)r0 * N + col)       = v0;
                *(float2*)(outf + (size_t)(r0 + 8) * N + col) = v1;
            }
        }
    }
}

// ---------------------------------------------------------------------------
// Flash attention (HMMA): 128 queries/CTA, 8 warps, fp16 in/out, fp32 softmax.
// Q pre-scaled by 1/8. grid = (T/128, B*H), block 256, dynamic smem.
// q-tiles scheduled LONGEST-FIRST (reversed) to fix causal load imbalance.
// ---------------------------------------------------------------------------
#define AT_ST 72                               // padded halves per row
#define ATQ_HALVES (128 * AT_ST)               // 9216
#define ATKV_HALVES (64 * AT_ST)               // 4608
static constexpr int ATTN_SMEM = (ATQ_HALVES + 4 * ATKV_HALVES) * 2;  // 55296 B

__global__ __launch_bounds__(256) void fattn_kernel(
    const __half* __restrict__ Qg, const __half* __restrict__ Kg,
    const __half* __restrict__ Vg, __half* __restrict__ y)
{
    extern __shared__ __align__(16) __half atsm[];
    __half* sQ = atsm;                              // 128 rows
    __half* sK = atsm + ATQ_HALVES;                 // [2][64 rows]
    __half* sV = atsm + ATQ_HALVES + 2 * ATKV_HALVES;

    const int tid = threadIdx.x, lane = tid & 31, w = tid >> 5;
    const int bh = blockIdx.y;
    const int q0 = (gridDim.x - 1 - blockIdx.x) * 128;   // longest tiles first
    const size_t base = (size_t)bh * TSEQ * HDIM;
    const int nt = q0 / 64 + 2;

#define LOADKV(kt, bufi) do {                                                  \
    const __half* kg = Kg + base + (size_t)(kt) * 64 * HDIM;                   \
    const __half* vg = Vg + base + (size_t)(kt) * 64 * HDIM;                   \
    __half* kd = sK + (bufi) * ATKV_HALVES;                                    \
    __half* vd = sV + (bufi) * ATKV_HALVES;                                    \
    _Pragma("unroll")                                                          \
    for (int i = 0; i < 2; i++) {                                              \
        const int c = tid * 2 + i;                                             \
        const int row = c >> 3, off = (c & 7) * 8;                             \
        cp_async16(smem_u32(kd + row * AT_ST + off), kg + row * HDIM + off);   \
        cp_async16(smem_u32(vd + row * AT_ST + off), vg + row * HDIM + off);   \
    }                                                                          \
} while (0)

    {
        const __half* qg = Qg + base + (size_t)q0 * HDIM;
#pragma unroll
        for (int i = 0; i < 4; i++) {
            const int c = tid * 4 + i;
            const int row = c >> 3, off = (c & 7) * 8;
            cp_async16(smem_u32(sQ + row * AT_ST + off), qg + row * HDIM + off);
        }
        LOADKV(0, 0);
        CP_COMMIT();
    }

    const uint32_t qbase = smem_u32(sQ) +
        (uint32_t)(((w * 16 + (lane & 15)) * AT_ST + (lane >> 4) * 8) * 2);
    const int nrow = (lane & 7) + ((lane >> 3) & 1) * 8;
    const int coff = (lane >> 4) * 8;
    const int er = lane >> 2, ec = (lane & 3) * 2;
    const int qwarp = q0 + w * 16;                  // warp's first q row

    float m0 = -1e30f, m1 = -1e30f, l0 = 0.f, l1 = 0.f;
    float o[8][4];
#pragma unroll
    for (int i = 0; i < 8; i++)
#pragma unroll
        for (int j = 0; j < 4; j++) o[i][j] = 0.f;

    for (int kt = 0; kt < nt; ++kt) {
        const int bufi = kt & 1;
        if (kt + 1 < nt) { LOADKV(kt + 1, bufi ^ 1); CP_COMMIT(); CP_WAIT(1); }
        else             { CP_WAIT(0); }
        __syncthreads();

        const bool active = (kt * 64) <= (qwarp + 15);
        if (active) {
            const uint32_t kb = smem_u32(sK + bufi * ATKV_HALVES);
            const uint32_t vb = smem_u32(sV + bufi * ATKV_HALVES);

            // ---- S = Q @ K^T (64 keys)
            float s[8][4];
#pragma unroll
            for (int i = 0; i < 8; i++)
#pragma unroll
                for (int j = 0; j < 4; j++) s[i][j] = 0.f;

#pragma unroll
            for (int ks = 0; ks < 4; ++ks) {
                uint32_t aQ[4];
                ldsm4(aQ, qbase + ks * 32);
#pragma unroll
                for (int nj = 0; nj < 4; nj++) {
                    uint32_t r[4];
                    ldsm4(r, kb + (uint32_t)(((nj * 16 + nrow) * AT_ST + ks * 16 + coff) * 2));
                    uint32_t bA[2] = { r[0], r[2] }, bB[2] = { r[1], r[3] };
                    mma16816(s[nj * 2],     aQ, bA);
                    mma16816(s[nj * 2 + 1], aQ, bB);
                }
            }

            // ---- causal mask (global indices; only near-diagonal tiles)
            if (kt * 64 + 63 > qwarp) {
                const int r0w = qwarp + er, r1w = r0w + 8;
                const int j0 = kt * 64;
#pragma unroll
                for (int n = 0; n < 8; n++) {
                    const int c0 = j0 + n * 8 + ec;
                    if (c0     > r0w) s[n][0] = -1e30f;
                    if (c0 + 1 > r0w) s[n][1] = -1e30f;
                    if (c0     > r1w) s[n][2] = -1e30f;
                    if (c0 + 1 > r1w) s[n][3] = -1e30f;
                }
            }

            // ---- online softmax
            float mx0 = -1e30f, mx1 = -1e30f;
#pragma unroll
            for (int n = 0; n < 8; n++) {
                mx0 = fmaxf(mx0, fmaxf(s[n][0], s[n][1]));
                mx1 = fmaxf(mx1, fmaxf(s[n][2], s[n][3]));
            }
            mx0 = fmaxf(mx0, __shfl_xor_sync(0xffffffffu, mx0, 1));
            mx0 = fmaxf(mx0, __shfl_xor_sync(0xffffffffu, mx0, 2));
            mx1 = fmaxf(mx1, __shfl_xor_sync(0xffffffffu, mx1, 1));
            mx1 = fmaxf(mx1, __shfl_xor_sync(0xffffffffu, mx1, 2));

            const float mn0 = fmaxf(m0, mx0), mn1 = fmaxf(m1, mx1);
            const float f0 = __expf(m0 - mn0), f1 = __expf(m1 - mn1);
            float sum0 = 0.f, sum1 = 0.f;
#pragma unroll
            for (int n = 0; n < 8; n++) {
                s[n][0] = __expf(s[n][0] - mn0); sum0 += s[n][0];
                s[n][1] = __expf(s[n][1] - mn0); sum0 += s[n][1];
                s[n][2] = __expf(s[n][2] - mn1); sum1 += s[n][2];
                s[n][3] = __expf(s[n][3] - mn1); sum1 += s[n][3];
            }
            sum0 += __shfl_xor_sync(0xffffffffu, sum0, 1);
            sum0 += __shfl_xor_sync(0xffffffffu, sum0, 2);
            sum1 += __shfl_xor_sync(0xffffffffu, sum1, 1);
            sum1 += __shfl_xor_sync(0xffffffffu, sum1, 2);
            l0 = l0 * f0 + sum0;
            l1 = l1 * f1 + sum1;
            m0 = mn0; m1 = mn1;
#pragma unroll
            for (int n = 0; n < 8; n++) {
                o[n][0] *= f0; o[n][1] *= f0;
                o[n][2] *= f1; o[n][3] *= f1;
            }

            // ---- O += P @ V
#pragma unroll
            for (int ks = 0; ks < 4; ++ks) {
                uint32_t aP[4];
                aP[0] = f2h2(s[ks * 2][0],     s[ks * 2][1]);
                aP[1] = f2h2(s[ks * 2][2],     s[ks * 2][3]);
                aP[2] = f2h2(s[ks * 2 + 1][0], s[ks * 2 + 1][1]);
                aP[3] = f2h2(s[ks * 2 + 1][2], s[ks * 2 + 1][3]);
#pragma unroll
                for (int ng = 0; ng < 4; ng++) {
                    uint32_t r[4];
                    ldsm4t(r, vb + (uint32_t)(((ks * 16 + nrow) * AT_ST + ng * 16 + coff) * 2));
                    uint32_t bA[2] = { r[0], r[1] }, bB[2] = { r[2], r[3] };
                    mma16816(o[ng * 2],     aP, bA);
                    mma16816(o[ng * 2 + 1], aP, bB);
                }
            }
        }
        __syncthreads();
    }
#undef LOADKV

    const float inv0 = 1.0f / l0, inv1 = 1.0f / l1;
    const int b = bh / NHEAD, h = bh - b * NHEAD;
    const int row0 = q0 + w * 16 + er;
    __half* yp = y + ((size_t)b * TSEQ + row0) * CEMB + h * HDIM;
#pragma unroll
    for (int ng = 0; ng < 8; ng++) {
        const int col = ng * 8 + ec;
        *(__half2*)(yp + col) = __floats2half2_rn(o[ng][0] * inv0, o[ng][1] * inv0);
        *(__half2*)(yp + (size_t)8 * CEMB + col) =
            __floats2half2_rn(o[ng][2] * inv1, o[ng][3] * inv1);
    }
}

// ---------------------------------------------------------------------------
// Launch
// ---------------------------------------------------------------------------
extern "C" void kernel_launch(void* const* d_in, const int* in_sizes, int n_in,
                              void* d_out, int out_size)
{
    const float* x           = (const float*)d_in[0];
    const float* ln1_g       = (const float*)d_in[1];
    const float* ln1_b       = (const float*)d_in[2];
    const float* w_attn      = (const float*)d_in[3];
    const float* b_attn      = (const float*)d_in[4];
    const float* w_attn_proj = (const float*)d_in[5];
    const float* b_attn_proj = (const float*)d_in[6];
    const float* ln2_g       = (const float*)d_in[7];
    const float* ln2_b       = (const float*)d_in[8];
    const float* w_fc        = (const float*)d_in[9];
    const float* b_fc        = (const float*)d_in[10];
    const float* w_mlp_proj  = (const float*)d_in[11];
    const float* b_mlp_proj  = (const float*)d_in[12];
    float* out = (float*)d_out;

    __half *p_lnh, *p_q, *p_k, *p_v, *p_atth, *p_fch, *p_wTa, *p_wTp, *p_wTf, *p_wTm;
    float *p_x1;
    cudaGetSymbolAddress((void**)&p_lnh,  g_lnh);
    cudaGetSymbolAddress((void**)&p_q,    g_q);
    cudaGetSymbolAddress((void**)&p_k,    g_k);
    cudaGetSymbolAddress((void**)&p_v,    g_v);
    cudaGetSymbolAddress((void**)&p_atth, g_atth);
    cudaGetSymbolAddress((void**)&p_x1,   g_x1);
    cudaGetSymbolAddress((void**)&p_fch,  g_fch);
    cudaGetSymbolAddress((void**)&p_wTa,  g_wTa);
    cudaGetSymbolAddress((void**)&p_wTp,  g_wTp);
    cudaGetSymbolAddress((void**)&p_wTf,  g_wTf);
    cudaGetSymbolAddress((void**)&p_wTm,  g_wTm);

    cudaFuncSetAttribute(gemm_hmma<1>, cudaFuncAttributeMaxDynamicSharedMemorySize, GEMM_SMEM);
    cudaFuncSetAttribute(gemm_hmma<2>, cudaFuncAttributeMaxDynamicSharedMemorySize, GEMM_SMEM);
    cudaFuncSetAttribute(gemm_hmma<3>, cudaFuncAttributeMaxDynamicSharedMemorySize, GEMM_SMEM);
    cudaFuncSetAttribute(fattn_kernel, cudaFuncAttributeMaxDynamicSharedMemorySize, ATTN_SMEM);

    // weight transposes (merged, one launch)
    wtrans_all<<<6912, dim3(32, 8)>>>(w_attn, p_wTa, w_attn_proj, p_wTp,
                                      w_fc, p_wTf, w_mlp_proj, p_wTm);

    // 1. LN1 -> fp16
    ln_kernel<<<NTOK, 256>>>(x, ln1_g, ln1_b, p_lnh);

    // 2. QKV -> split fp16 Q (x1/8), K, V in [B*H, T, 64]
    gemm_hmma<3><<<dim3(2304 / BN, NTOK / BM), 256, GEMM_SMEM>>>(
        NTOK, 2304, CEMB, p_lnh, p_wTa, b_attn, nullptr, nullptr, nullptr,
        p_q, p_k, p_v);

    // 3. flash attention -> fp16 [token][C]  (longest q-tiles first)
    fattn_kernel<<<dim3(TSEQ / 128, 2 * NHEAD), 256, ATTN_SMEM>>>(p_q, p_k, p_v, p_atth);

    // 4. x1 = x + att @ w_attn_proj + b (fp32)
    gemm_hmma<1><<<dim3(CEMB / BN, NTOK / BM), 256, GEMM_SMEM>>>(
        NTOK, CEMB, CEMB, p_atth, p_wTp, b_attn_proj, x, p_x1, nullptr,
        nullptr, nullptr, nullptr);

    // 5. LN2 -> fp16
    ln_kernel<<<NTOK, 256>>>(p_x1, ln2_g, ln2_b, p_lnh);

    // 6. fc = gelu(...) -> fp16
    gemm_hmma<2><<<dim3(3072 / BN, NTOK / BM), 256, GEMM_SMEM>>>(
        NTOK, 3072, CEMB, p_lnh, p_wTf, b_fc, nullptr, nullptr, p_fch,
        nullptr, nullptr, nullptr);

    // 7. out = x1 + fc @ w_mlp_proj + b (fp32)
    gemm_hmma<1><<<dim3(CEMB / BN, NTOK / BM), 256, GEMM_SMEM>>>(
        NTOK, CEMB, 4 * CEMB, p_fch, p_wTm, b_mlp_proj, p_x1, out, nullptr,
        nullptr, nullptr, nullptr);
}